// round 11
// baseline (speedup 1.0000x reference)
#include <cuda_runtime.h>
#include <cuda_bf16.h>

#define EMB   1024
#define SEQ   1024
#define BATCH 32
#define KDIM  1024
#define NROWS (BATCH*SEQ)
#define NELEM ((size_t)NROWS*EMB)
#define NSS   ((size_t)BATCH*SEQ*SEQ)
#define WSZ   ((size_t)1024*1024)

// GEMM tiling
#define BM 128
#define BN 128
#define BK 32
#define NQ  (KDIM/BK)   // 32 K-chunks
#define NST 3           // cp.async pipeline depth
#define LDS 40          // padded smem row stride (elements)

// per-stage smem layout (bytes): four 128x32 bf16 tiles, rows padded to LDS
#define TILE_B      (BM*LDS*2)          // 10240
#define OFF_AH      0
#define OFF_AL      (TILE_B)
#define OFF_BH      (2*TILE_B)
#define OFF_BL      (3*TILE_B)
#define STAGE_B     (4*TILE_B)          // 40960
#define SMEM_DYN    (NST*STAGE_B)       // 122880

// ---------------- PTX helpers (portable sm_80+ only) ----------------
__device__ __forceinline__ unsigned smem_u32(const void* p) {
    unsigned a;
    asm("{ .reg .u64 t; cvta.to.shared.u64 t, %1; cvt.u32.u64 %0, t; }" : "=r"(a) : "l"(p));
    return a;
}
#define CPASYNC16(dst, src) \
    asm volatile("cp.async.cg.shared.global [%0], [%1], 16;" :: "r"(dst), "l"(src))
#define CPCOMMIT() asm volatile("cp.async.commit_group;" ::: "memory")
#define CPWAIT(n)  asm volatile("cp.async.wait_group %0;" :: "n"(n) : "memory")
#define LDSM4(r0, r1, r2, r3, a) \
    asm volatile("ldmatrix.sync.aligned.m8n8.x4.shared.b16 {%0,%1,%2,%3}, [%4];" \
        : "=r"(r0), "=r"(r1), "=r"(r2), "=r"(r3) : "r"(a))
#define MMA(c, a, b) \
    asm volatile("mma.sync.aligned.m16n8k16.row.col.f32.bf16.bf16.f32 " \
        "{%0,%1,%2,%3}, {%4,%5,%6,%7}, {%8,%9}, {%0,%1,%2,%3};" \
        : "+f"((c)[0]), "+f"((c)[1]), "+f"((c)[2]), "+f"((c)[3]) \
        : "r"((a)[0]), "r"((a)[1]), "r"((a)[2]), "r"((a)[3]), "r"((b)[0]), "r"((b)[1]))

__device__ __forceinline__ void split2(float a, float b, __nv_bfloat162& h, __nv_bfloat162& l) {
    h.x = __float2bfloat16_rn(a); h.y = __float2bfloat16_rn(b);
    l.x = __float2bfloat16_rn(a - __bfloat162float(h.x));
    l.y = __float2bfloat16_rn(b - __bfloat162float(h.y));
}

// ---------------- scratch ----------------
__device__ float g_x[NELEM];                              // residual stream (fp32)
__device__ float g_y[NELEM];                              // x2 (fp32)
__device__ __nv_bfloat16 g_h_hi[NELEM],  g_h_lo[NELEM];
__device__ __nv_bfloat16 g_q_hi[NELEM],  g_q_lo[NELEM];
__device__ __nv_bfloat16 g_k_hi[NELEM],  g_k_lo[NELEM];
__device__ __nv_bfloat16 g_vT_hi[NELEM], g_vT_lo[NELEM];
__device__ __nv_bfloat16 g_w_hi[NSS],    g_w_lo[NSS];
__device__ __nv_bfloat16 g_W_hi[6*WSZ],  g_W_lo[6*WSZ];

// ---------------------------------------------------------------------------
// Tensor-core GEMM: C = alpha*(A @ B^T) [+bias] [+Rsd] [relu]
// bf16 hi/lo split (3 products: Ah·Bh + Ah·Bl + Al·Bh) with all 4 tiles staged
// once per K-chunk. 32 chunks, 3-deep cp.async pipeline, 1 barrier per chunk.
// grid = (N/128, M/128, Z). Outputs: fp32 Cf and/or split Ch/Cl (trans=1:
// C[r,e] stored at [(b*1024+e)*1024 + s], r = b*1024+s).
// ---------------------------------------------------------------------------
__global__ void __launch_bounds__(256, 1) gemm_mma(
    const __nv_bfloat16* __restrict__ Ah, const __nv_bfloat16* __restrict__ Al, size_t sA,
    const __nv_bfloat16* __restrict__ Bh, const __nv_bfloat16* __restrict__ Bl, size_t sB,
    const float* __restrict__ bias,
    const float* __restrict__ Rsd, size_t sR,
    float alpha, int relu,
    float* __restrict__ Cf,
    __nv_bfloat16* __restrict__ Ch, __nv_bfloat16* __restrict__ Cl,
    int trans, size_t sC)
{
    extern __shared__ __align__(16) char dynsm[];
    const unsigned dynB = smem_u32(dynsm);

    const int tid = threadIdx.x, wid = tid >> 5, lane = tid & 31;
    const int wm = wid & 3, wn = wid >> 2;          // warp grid 4(m) x 2(n)
    const int g = lane >> 2, tig = lane & 3;
    const int bm = blockIdx.y * BM, bn = blockIdx.x * BN;
    const int z = blockIdx.z;
    Ah += (size_t)z * sA;  Al += (size_t)z * sA;
    Bh += (size_t)z * sB;  Bl += (size_t)z * sB;

    // staging: thread -> (row, 8-elem col group); 2 iters cover 128 rows
    const int srow = tid >> 2, sc = (tid & 3) * 8;
    // ldmatrix per-thread base offsets (bytes) — validated in R10
    const unsigned aoff0 = (unsigned)((wm * 32 + (lane & 15)) * LDS + (lane >> 4) * 8) * 2;
    const unsigned boff0 = (unsigned)((wn * 64 + (lane >> 4) * 8 + (lane & 7)) * LDS
                                      + ((lane >> 3) & 1) * 8) * 2;

    float acc[2][8][4];
#pragma unroll
    for (int a = 0; a < 2; a++)
#pragma unroll
        for (int b = 0; b < 8; b++)
#pragma unroll
            for (int c = 0; c < 4; c++) acc[a][b][c] = 0.f;

    auto stage = [&](int q, int buf) {
        const int ko = q * BK;
        const unsigned d = dynB + (unsigned)buf * STAGE_B;
#pragma unroll
        for (int i = 0; i < 2; i++) {
            const int row = srow + i * 64;
            const unsigned so = (unsigned)(row * LDS + sc) * 2;
            const size_t ga = (size_t)(bm + row) * KDIM + ko + sc;
            const size_t gb = (size_t)(bn + row) * KDIM + ko + sc;
            CPASYNC16(d + OFF_AH + so, (const void*)(Ah + ga));
            CPASYNC16(d + OFF_AL + so, (const void*)(Al + ga));
            CPASYNC16(d + OFF_BH + so, (const void*)(Bh + gb));
            CPASYNC16(d + OFF_BL + so, (const void*)(Bl + gb));
        }
    };

    auto compute = [&](int buf) {
        const unsigned sb = dynB + (unsigned)buf * STAGE_B;
#pragma unroll
        for (int ks = 0; ks < 2; ks++) {
            const unsigned kof = (unsigned)(ks * 16) * 2;
            unsigned afh[2][4], afl[2][4];
#pragma unroll
            for (int mi = 0; mi < 2; mi++) {
                const unsigned mof = aoff0 + (unsigned)(mi * 16 * LDS) * 2 + kof;
                LDSM4(afh[mi][0], afh[mi][1], afh[mi][2], afh[mi][3], sb + OFF_AH + mof);
                LDSM4(afl[mi][0], afl[mi][1], afl[mi][2], afl[mi][3], sb + OFF_AL + mof);
            }
            unsigned bfh[8][2], bfl[8][2];
#pragma unroll
            for (int jp = 0; jp < 4; jp++) {
                const unsigned nof = boff0 + (unsigned)(jp * 16 * LDS) * 2 + kof;
                unsigned r0, r1, r2, r3;
                LDSM4(r0, r1, r2, r3, sb + OFF_BH + nof);
                bfh[jp*2][0] = r0; bfh[jp*2][1] = r1;
                bfh[jp*2+1][0] = r2; bfh[jp*2+1][1] = r3;
                LDSM4(r0, r1, r2, r3, sb + OFF_BL + nof);
                bfl[jp*2][0] = r0; bfl[jp*2][1] = r1;
                bfl[jp*2+1][0] = r2; bfl[jp*2+1][1] = r3;
            }
#pragma unroll
            for (int mi = 0; mi < 2; mi++)
#pragma unroll
                for (int ni = 0; ni < 8; ni++)
                    MMA(acc[mi][ni], afh[mi], bfh[ni]);
#pragma unroll
            for (int mi = 0; mi < 2; mi++)
#pragma unroll
                for (int ni = 0; ni < 8; ni++)
                    MMA(acc[mi][ni], afh[mi], bfl[ni]);
#pragma unroll
            for (int mi = 0; mi < 2; mi++)
#pragma unroll
                for (int ni = 0; ni < 8; ni++)
                    MMA(acc[mi][ni], afl[mi], bfh[ni]);
        }
    };

    // prologue: prefetch stages 0..NST-2
#pragma unroll
    for (int s = 0; s < NST - 1; s++) { stage(s, s); CPCOMMIT(); }

    for (int q = 0; q < NQ; q++) {
        CPWAIT(NST - 2);
        __syncthreads();
        // prefetch into the buffer computed in iteration q-1 (barrier-protected)
        if (q + NST - 1 < NQ) stage(q + NST - 1, (q + NST - 1) % NST);
        CPCOMMIT();
        compute(q % NST);
    }

    // ---- epilogue ----
#pragma unroll
    for (int mi = 0; mi < 2; mi++) {
#pragma unroll
        for (int half = 0; half < 2; half++) {
            const int r = bm + wm * 32 + mi * 16 + g + half * 8;
#pragma unroll
            for (int ni = 0; ni < 8; ni++) {
                const int cc = bn + wn * 64 + ni * 8 + tig * 2;
                float v0 = acc[mi][ni][half * 2 + 0] * alpha;
                float v1 = acc[mi][ni][half * 2 + 1] * alpha;
                if (bias) { v0 += __ldg(bias + cc); v1 += __ldg(bias + cc + 1); }
                if (Rsd) {
                    const float2 rv = *(const float2*)(Rsd + (size_t)z * sR
                                                       + (size_t)r * 1024 + cc);
                    v0 += rv.x; v1 += rv.y;
                }
                if (relu) { v0 = fmaxf(v0, 0.f); v1 = fmaxf(v1, 0.f); }
                if (Cf)
                    *(float2*)(Cf + (size_t)z * sC + (size_t)r * 1024 + cc)
                        = make_float2(v0, v1);
                if (Ch) {
                    if (!trans) {
                        __nv_bfloat162 h2, l2;
                        split2(v0, v1, h2, l2);
                        *(__nv_bfloat162*)(Ch + (size_t)z * sC + (size_t)r * 1024 + cc) = h2;
                        *(__nv_bfloat162*)(Cl + (size_t)z * sC + (size_t)r * 1024 + cc) = l2;
                    } else {
                        const size_t b = (size_t)r >> 10, s5 = (size_t)r & 1023;
                        const size_t i0 = ((b << 10) + (size_t)cc)     * 1024 + s5;
                        const size_t i1 = ((b << 10) + (size_t)cc + 1) * 1024 + s5;
                        __nv_bfloat16 h0 = __float2bfloat16_rn(v0);
                        Ch[i0] = h0; Cl[i0] = __float2bfloat16_rn(v0 - __bfloat162float(h0));
                        __nv_bfloat16 h1 = __float2bfloat16_rn(v1);
                        Ch[i1] = h1; Cl[i1] = __float2bfloat16_rn(v1 - __bfloat162float(h1));
                    }
                }
            }
        }
    }
}

// ---------------------------------------------------------------------------
__global__ __launch_bounds__(256) void embed_k(const float* __restrict__ x,
                                               const float* __restrict__ pe,
                                               float* __restrict__ o) {
    size_t i = (size_t)blockIdx.x * 256 + threadIdx.x;
    const float4 a = ((const float4*)x)[i];
    const float4 p = ((const float4*)pe)[i & ((size_t)SEQ * EMB / 4 - 1)];
    ((float4*)o)[i] = make_float4(32.f*a.x+p.x, 32.f*a.y+p.y, 32.f*a.z+p.z, 32.f*a.w+p.w);
}

__global__ __launch_bounds__(256) void split_k(const float* __restrict__ in,
                                               __nv_bfloat16* __restrict__ oh,
                                               __nv_bfloat16* __restrict__ ol) {
    size_t i = ((size_t)blockIdx.x * 256 + threadIdx.x) * 4;
    float4 v = *(const float4*)(in + i);
    __nv_bfloat162 h0, l0, h1, l1;
    split2(v.x, v.y, h0, l0); split2(v.z, v.w, h1, l1);
    *(__nv_bfloat162*)(oh + i)     = h0; *(__nv_bfloat162*)(oh + i + 2) = h1;
    *(__nv_bfloat162*)(ol + i)     = l0; *(__nv_bfloat162*)(ol + i + 2) = l1;
}

__global__ __launch_bounds__(256) void ln_split_k(const float* __restrict__ in,
                                                  const float* __restrict__ g,
                                                  const float* __restrict__ b,
                                                  __nv_bfloat16* __restrict__ oh,
                                                  __nv_bfloat16* __restrict__ ol) {
    const size_t row = blockIdx.x;
    const int t = threadIdx.x;
    const float4 v = ((const float4*)(in + row * EMB))[t];
    float s  = v.x + v.y + v.z + v.w;
    float ss = v.x*v.x + v.y*v.y + v.z*v.z + v.w*v.w;
#pragma unroll
    for (int o = 16; o > 0; o >>= 1) {
        s  += __shfl_xor_sync(0xFFFFFFFFu, s, o);
        ss += __shfl_xor_sync(0xFFFFFFFFu, ss, o);
    }
    __shared__ float sh_s[8], sh_ss[8];
    if ((t & 31) == 0) { sh_s[t >> 5] = s; sh_ss[t >> 5] = ss; }
    __syncthreads();
    float ts = 0.f, tss = 0.f;
#pragma unroll
    for (int i = 0; i < 8; i++) { ts += sh_s[i]; tss += sh_ss[i]; }
    const float mu  = ts * (1.f / EMB);
    const float inv = rsqrtf(tss * (1.f / EMB) - mu * mu + 1e-5f);
    const float4 gg = ((const float4*)g)[t];
    const float4 bb = ((const float4*)b)[t];
    float r0 = (v.x - mu) * inv * gg.x + bb.x;
    float r1 = (v.y - mu) * inv * gg.y + bb.y;
    float r2 = (v.z - mu) * inv * gg.z + bb.z;
    float r3 = (v.w - mu) * inv * gg.w + bb.w;
    size_t o4 = row * EMB + (size_t)t * 4;
    __nv_bfloat162 h0, l0, h1, l1;
    split2(r0, r1, h0, l0); split2(r2, r3, h1, l1);
    *(__nv_bfloat162*)(oh + o4)     = h0; *(__nv_bfloat162*)(oh + o4 + 2) = h1;
    *(__nv_bfloat162*)(ol + o4)     = l0; *(__nv_bfloat162*)(ol + o4 + 2) = l1;
}

__global__ __launch_bounds__(256) void softmax_k(float* __restrict__ w,
                                                 __nv_bfloat16* __restrict__ oh,
                                                 __nv_bfloat16* __restrict__ ol) {
    const size_t row = blockIdx.x;
    float4* p = (float4*)(w + row * SEQ);
    const int t = threadIdx.x;
    float4 v = p[t];
    float m = fmaxf(fmaxf(v.x, v.y), fmaxf(v.z, v.w));
#pragma unroll
    for (int o = 16; o > 0; o >>= 1) m = fmaxf(m, __shfl_xor_sync(0xFFFFFFFFu, m, o));
    __shared__ float shm[8], shs[8];
    if ((t & 31) == 0) shm[t >> 5] = m;
    __syncthreads();
    float M = shm[0];
#pragma unroll
    for (int i = 1; i < 8; i++) M = fmaxf(M, shm[i]);
    float4 e;
    e.x = __expf(v.x - M); e.y = __expf(v.y - M);
    e.z = __expf(v.z - M); e.w = __expf(v.w - M);
    float s = e.x + e.y + e.z + e.w;
#pragma unroll
    for (int o = 16; o > 0; o >>= 1) s += __shfl_xor_sync(0xFFFFFFFFu, s, o);
    if ((t & 31) == 0) shs[t >> 5] = s;
    __syncthreads();
    float S = 0.f;
#pragma unroll
    for (int i = 0; i < 8; i++) S += shs[i];
    const float inv = 1.f / S;
    e.x *= inv; e.y *= inv; e.z *= inv; e.w *= inv;
    p[t] = e;
    size_t o4 = row * SEQ + (size_t)t * 4;
    __nv_bfloat162 h0, l0, h1, l1;
    split2(e.x, e.y, h0, l0); split2(e.z, e.w, h1, l1);
    *(__nv_bfloat162*)(oh + o4)     = h0; *(__nv_bfloat162*)(oh + o4 + 2) = h1;
    *(__nv_bfloat162*)(ol + o4)     = l0; *(__nv_bfloat162*)(ol + o4 + 2) = l1;
}

__global__ __launch_bounds__(256) void cls_k(const float* __restrict__ X,
                                             const float* __restrict__ Wc,
                                             const float* __restrict__ bc,
                                             float* __restrict__ out) {
    const int b = blockIdx.x >> 1, o = blockIdx.x & 1;
    const int t = threadIdx.x;
    const float4 a = ((const float4*)(X + (size_t)b * SEQ * EMB))[t];
    const float4 w = ((const float4*)(Wc + (size_t)o * EMB))[t];
    float s = a.x*w.x + a.y*w.y + a.z*w.z + a.w*w.w;
#pragma unroll
    for (int off = 16; off > 0; off >>= 1) s += __shfl_xor_sync(0xFFFFFFFFu, s, off);
    __shared__ float sh[8];
    if ((t & 31) == 0) sh[t >> 5] = s;
    __syncthreads();
    if (t == 0) {
        float S = 0.f;
#pragma unroll
        for (int i = 0; i < 8; i++) S += sh[i];
        out[b * 2 + o] = S + bc[o];
    }
}

// ---------------------------------------------------------------------------
extern "C" void kernel_launch(void* const* d_in, const int* in_sizes, int n_in,
                              void* d_out, int out_size) {
    (void)in_sizes; (void)n_in; (void)out_size;
    const float* x     = (const float*)d_in[0];
    const float* pe    = (const float*)d_in[1];
    const float* ln1_g = (const float*)d_in[2];
    const float* ln1_b = (const float*)d_in[3];
    const float* Wq = (const float*)d_in[4];  const float* bq = (const float*)d_in[5];
    const float* Wk = (const float*)d_in[6];  const float* bk = (const float*)d_in[7];
    const float* Wv = (const float*)d_in[8];  const float* bv = (const float*)d_in[9];
    const float* Wo = (const float*)d_in[10]; const float* bo = (const float*)d_in[11];
    const float* ln2_g = (const float*)d_in[12];
    const float* ln2_b = (const float*)d_in[13];
    const float* W1 = (const float*)d_in[14]; const float* b1 = (const float*)d_in[15];
    const float* W2 = (const float*)d_in[16]; const float* b2 = (const float*)d_in[17];
    const float* Wc = (const float*)d_in[18]; const float* bc = (const float*)d_in[19];

    float* out = (float*)d_out;
    float* w1 = out + 64;
    float* w2 = w1 + NSS;

    float *px, *py;
    __nv_bfloat16 *hh, *hl, *qh, *ql, *kh, *kl, *vh, *vl, *wh, *wl, *Wh, *Wl;
    cudaGetSymbolAddress((void**)&px, g_x);
    cudaGetSymbolAddress((void**)&py, g_y);
    cudaGetSymbolAddress((void**)&hh, g_h_hi);  cudaGetSymbolAddress((void**)&hl, g_h_lo);
    cudaGetSymbolAddress((void**)&qh, g_q_hi);  cudaGetSymbolAddress((void**)&ql, g_q_lo);
    cudaGetSymbolAddress((void**)&kh, g_k_hi);  cudaGetSymbolAddress((void**)&kl, g_k_lo);
    cudaGetSymbolAddress((void**)&vh, g_vT_hi); cudaGetSymbolAddress((void**)&vl, g_vT_lo);
    cudaGetSymbolAddress((void**)&wh, g_w_hi);  cudaGetSymbolAddress((void**)&wl, g_w_lo);
    cudaGetSymbolAddress((void**)&Wh, g_W_hi);  cudaGetSymbolAddress((void**)&Wl, g_W_lo);

    cudaFuncSetAttribute(gemm_mma, cudaFuncAttributeMaxDynamicSharedMemorySize, SMEM_DYN);

    const size_t sSE = (size_t)SEQ * EMB;
    const size_t sSS = (size_t)SEQ * SEQ;

    // weight splits (Wq,Wk,Wv,Wo,W1,W2)
    const float* Ws[6] = {Wq, Wk, Wv, Wo, W1, W2};
    for (int i = 0; i < 6; i++)
        split_k<<<1024, 256>>>(Ws[i], Wh + (size_t)i * WSZ, Wl + (size_t)i * WSZ);
    __nv_bfloat16 *Wqh = Wh,         *Wql = Wl;
    __nv_bfloat16 *Wkh = Wh + WSZ,   *Wkl = Wl + WSZ;
    __nv_bfloat16 *Wvh = Wh + 2*WSZ, *Wvl = Wl + 2*WSZ;
    __nv_bfloat16 *Woh = Wh + 3*WSZ, *Wol = Wl + 3*WSZ;
    __nv_bfloat16 *W1h = Wh + 4*WSZ, *W1l = Wl + 4*WSZ;
    __nv_bfloat16 *W2h = Wh + 5*WSZ, *W2l = Wl + 5*WSZ;

    // x1 = 32*x + pe
    embed_k<<<(unsigned)(NELEM / 4 / 256), 256>>>(x, pe, px);

    const dim3 gP(EMB / BN, NROWS / BM, 1);     // (8, 256, 1)
    const dim3 gB(SEQ / BN, SEQ / BM, BATCH);   // (8, 8, 32)

    for (int blk = 0; blk < 2; blk++) {
        float* wout = blk ? w2 : w1;
        // h = LN1(x) (split)
        ln_split_k<<<NROWS, 256>>>(px, ln1_g, ln1_b, hh, hl);
        // q = h@Wq^T + bq (split)
        gemm_mma<<<gP, 256, SMEM_DYN>>>(hh, hl, 0, Wqh, Wql, 0, bq, nullptr, 0, 1.f, 0,
                                        nullptr, qh, ql, 0, 0);
        // k
        gemm_mma<<<gP, 256, SMEM_DYN>>>(hh, hl, 0, Wkh, Wkl, 0, bk, nullptr, 0, 1.f, 0,
                                        nullptr, kh, kl, 0, 0);
        // v (transposed split: vT[b,e,s])
        gemm_mma<<<gP, 256, SMEM_DYN>>>(hh, hl, 0, Wvh, Wvl, 0, bv, nullptr, 0, 1.f, 0,
                                        nullptr, vh, vl, 1, 0);
        // scores = q k^T / 32 -> fp32 wout (straight into d_out region)
        gemm_mma<<<gB, 256, SMEM_DYN>>>(qh, ql, sSE, kh, kl, sSE, nullptr, nullptr, 0,
                                        0.03125f, 0, wout, nullptr, nullptr, 0, sSS);
        // softmax in place + split
        softmax_k<<<NROWS, 256>>>(wout, wh, wl);
        // attn = w @ vT^T -> split into h (reuse)
        gemm_mma<<<gB, 256, SMEM_DYN>>>(wh, wl, sSS, vh, vl, sSE, nullptr, nullptr, 0,
                                        1.f, 0, nullptr, hh, hl, 0, sSE);
        // x2 = x1 + attn@Wo^T + bo -> fp32 py
        gemm_mma<<<gP, 256, SMEM_DYN>>>(hh, hl, 0, Woh, Wol, 0, bo, px, 0, 1.f, 0,
                                        py, nullptr, nullptr, 0, 0);
        // h = LN2(x2) (split)
        ln_split_k<<<NROWS, 256>>>(py, ln2_g, ln2_b, hh, hl);
        // f1 = relu(h@W1^T + b1) -> split into q (reuse)
        gemm_mma<<<gP, 256, SMEM_DYN>>>(hh, hl, 0, W1h, W1l, 0, b1, nullptr, 0, 1.f, 1,
                                        nullptr, qh, ql, 0, 0);
        // x3 = x2 + f1@W2^T + b2 -> fp32 px
        gemm_mma<<<gP, 256, SMEM_DYN>>>(qh, ql, 0, W2h, W2l, 0, b2, py, 0, 1.f, 0,
                                        px, nullptr, nullptr, 0, 0);
    }

    cls_k<<<64, 256>>>(px, Wc, bc, out);
}

// round 12
// speedup vs baseline: 1.4715x; 1.4715x over previous
#include <cuda_runtime.h>
#include <cuda_fp16.h>

#define EMB   1024
#define SEQ   1024
#define BATCH 32
#define KDIM  1024
#define NROWS (BATCH*SEQ)
#define NELEM ((size_t)NROWS*EMB)
#define NSS   ((size_t)BATCH*SEQ*SEQ)
#define WSZ   ((size_t)1024*1024)

// GEMM tiling
#define BM 128
#define BN 128
#define BK 32
#define NQ  (KDIM/BK)   // 32 K-chunks
#define NST 4           // cp.async pipeline depth
#define LDS 40          // padded smem row stride (elements)

// per-stage smem: three 128x32 fp16 tiles (Ah, Al, Bh), rows padded to LDS
#define TILE_B      (BM*LDS*2)          // 10240
#define OFF_AH      0
#define OFF_AL      (TILE_B)
#define OFF_BH      (2*TILE_B)
#define STAGE_B     (3*TILE_B)          // 30720
#define SMEM_DYN    (NST*STAGE_B)       // 122880

// ---------------- PTX helpers (portable sm_80+ only) ----------------
__device__ __forceinline__ unsigned smem_u32(const void* p) {
    unsigned a;
    asm("{ .reg .u64 t; cvta.to.shared.u64 t, %1; cvt.u32.u64 %0, t; }" : "=r"(a) : "l"(p));
    return a;
}
#define CPASYNC16(dst, src) \
    asm volatile("cp.async.cg.shared.global [%0], [%1], 16;" :: "r"(dst), "l"(src))
#define CPCOMMIT() asm volatile("cp.async.commit_group;" ::: "memory")
#define CPWAIT(n)  asm volatile("cp.async.wait_group %0;" :: "n"(n) : "memory")
#define LDSM4(r0, r1, r2, r3, a) \
    asm volatile("ldmatrix.sync.aligned.m8n8.x4.shared.b16 {%0,%1,%2,%3}, [%4];" \
        : "=r"(r0), "=r"(r1), "=r"(r2), "=r"(r3) : "r"(a))
#define MMA(c, a, b) \
    asm volatile("mma.sync.aligned.m16n8k16.row.col.f32.f16.f16.f32 " \
        "{%0,%1,%2,%3}, {%4,%5,%6,%7}, {%8,%9}, {%0,%1,%2,%3};" \
        : "+f"((c)[0]), "+f"((c)[1]), "+f"((c)[2]), "+f"((c)[3]) \
        : "r"((a)[0]), "r"((a)[1]), "r"((a)[2]), "r"((a)[3]), "r"((b)[0]), "r"((b)[1]))

__device__ __forceinline__ void split2(float a, float b, __half2& h, __half2& l) {
    __half ha = __float2half_rn(a), hb = __float2half_rn(b);
    h = __halves2half2(ha, hb);
    l = __halves2half2(__float2half_rn(a - __half2float(ha)),
                       __float2half_rn(b - __half2float(hb)));
}

// ---------------- scratch ----------------
__device__ float g_x[NELEM];                       // residual stream (fp32)
__device__ float g_y[NELEM];                       // x2 (fp32)
__device__ __half g_h_hi[NELEM],  g_h_lo[NELEM];   // LN out (A-role: hi+lo)
__device__ __half g_q_hi[NELEM],  g_q_lo[NELEM];   // q / f1 (A-role)
__device__ __half g_k_hi[NELEM];                   // k (B-role: hi only)
__device__ __half g_vT_hi[NELEM];                  // v transposed (B-role)
__device__ __half g_w_hi[NSS],    g_w_lo[NSS];     // softmax (A-role)
__device__ __half g_W_hi[6*WSZ];                   // weights (B-role)

// ---------------------------------------------------------------------------
// Tensor-core GEMM: C = alpha*(A @ B^T) [+bias] [+Rsd] [relu]
// fp16 2-product split: A = Ah + Al (fp16 hi/lo), B truncated to fp16 hi.
// C = Ah·Bh + Al·Bh. 32 K-chunks, 4-deep cp.async pipeline, 1 barrier/chunk.
// grid = (N/128, M/128, Z). Outputs: fp32 Cf and/or fp16 Ch[+Cl] (trans=1:
// C[r,e] stored at [(b*1024+e)*1024 + s], r = b*1024+s; hi only).
// ---------------------------------------------------------------------------
__global__ void __launch_bounds__(256, 1) gemm_mma(
    const __half* __restrict__ Ah, const __half* __restrict__ Al, size_t sA,
    const __half* __restrict__ Bh, size_t sB,
    const float* __restrict__ bias,
    const float* __restrict__ Rsd, size_t sR,
    float alpha, int relu,
    float* __restrict__ Cf,
    __half* __restrict__ Ch, __half* __restrict__ Cl,
    int trans, size_t sC)
{
    extern __shared__ __align__(16) char dynsm[];
    const unsigned dynB = smem_u32(dynsm);

    const int tid = threadIdx.x, wid = tid >> 5, lane = tid & 31;
    const int wm = wid & 3, wn = wid >> 2;          // warp grid 4(m) x 2(n)
    const int g = lane >> 2, tig = lane & 3;
    const int bm = blockIdx.y * BM, bn = blockIdx.x * BN;
    const int z = blockIdx.z;
    Ah += (size_t)z * sA;  Al += (size_t)z * sA;
    Bh += (size_t)z * sB;

    // staging: thread -> (row, 8-elem col group); 2 iters cover 128 rows
    const int srow = tid >> 2, sc = (tid & 3) * 8;
    // ldmatrix per-thread base offsets (bytes) — validated mapping
    const unsigned aoff0 = (unsigned)((wm * 32 + (lane & 15)) * LDS + (lane >> 4) * 8) * 2;
    const unsigned boff0 = (unsigned)((wn * 64 + (lane >> 4) * 8 + (lane & 7)) * LDS
                                      + ((lane >> 3) & 1) * 8) * 2;

    float acc[2][8][4];
#pragma unroll
    for (int a = 0; a < 2; a++)
#pragma unroll
        for (int b = 0; b < 8; b++)
#pragma unroll
            for (int c = 0; c < 4; c++) acc[a][b][c] = 0.f;

    auto stage = [&](int q, int buf) {
        const int ko = q * BK;
        const unsigned d = dynB + (unsigned)buf * STAGE_B;
#pragma unroll
        for (int i = 0; i < 2; i++) {
            const int row = srow + i * 64;
            const unsigned so = (unsigned)(row * LDS + sc) * 2;
            const size_t ga = (size_t)(bm + row) * KDIM + ko + sc;
            const size_t gb = (size_t)(bn + row) * KDIM + ko + sc;
            CPASYNC16(d + OFF_AH + so, (const void*)(Ah + ga));
            CPASYNC16(d + OFF_AL + so, (const void*)(Al + ga));
            CPASYNC16(d + OFF_BH + so, (const void*)(Bh + gb));
        }
    };

    auto compute = [&](int buf) {
        const unsigned sb = dynB + (unsigned)buf * STAGE_B;
#pragma unroll
        for (int ks = 0; ks < 2; ks++) {
            const unsigned kof = (unsigned)(ks * 16) * 2;
            unsigned afh[2][4], afl[2][4];
#pragma unroll
            for (int mi = 0; mi < 2; mi++) {
                const unsigned mof = aoff0 + (unsigned)(mi * 16 * LDS) * 2 + kof;
                LDSM4(afh[mi][0], afh[mi][1], afh[mi][2], afh[mi][3], sb + OFF_AH + mof);
                LDSM4(afl[mi][0], afl[mi][1], afl[mi][2], afl[mi][3], sb + OFF_AL + mof);
            }
            unsigned bfh[8][2];
#pragma unroll
            for (int jp = 0; jp < 4; jp++) {
                const unsigned nof = boff0 + (unsigned)(jp * 16 * LDS) * 2 + kof;
                unsigned r0, r1, r2, r3;
                LDSM4(r0, r1, r2, r3, sb + OFF_BH + nof);
                bfh[jp*2][0] = r0; bfh[jp*2][1] = r1;
                bfh[jp*2+1][0] = r2; bfh[jp*2+1][1] = r3;
            }
            // 16 independent accumulators between RAW reuses -> latency hidden
#pragma unroll
            for (int mi = 0; mi < 2; mi++)
#pragma unroll
                for (int ni = 0; ni < 8; ni++)
                    MMA(acc[mi][ni], afh[mi], bfh[ni]);
#pragma unroll
            for (int mi = 0; mi < 2; mi++)
#pragma unroll
                for (int ni = 0; ni < 8; ni++)
                    MMA(acc[mi][ni], afl[mi], bfh[ni]);
        }
    };

    // prologue: prefetch stages 0..NST-2
#pragma unroll
    for (int s = 0; s < NST - 1; s++) { stage(s, s); CPCOMMIT(); }

    for (int q = 0; q < NQ; q++) {
        CPWAIT(NST - 2);
        __syncthreads();
        if (q + NST - 1 < NQ) stage(q + NST - 1, (q + NST - 1) & (NST - 1));
        CPCOMMIT();
        compute(q & (NST - 1));
    }

    // ---- epilogue ----
#pragma unroll
    for (int mi = 0; mi < 2; mi++) {
#pragma unroll
        for (int half = 0; half < 2; half++) {
            const int r = bm + wm * 32 + mi * 16 + g + half * 8;
#pragma unroll
            for (int ni = 0; ni < 8; ni++) {
                const int cc = bn + wn * 64 + ni * 8 + tig * 2;
                float v0 = acc[mi][ni][half * 2 + 0] * alpha;
                float v1 = acc[mi][ni][half * 2 + 1] * alpha;
                if (bias) { v0 += __ldg(bias + cc); v1 += __ldg(bias + cc + 1); }
                if (Rsd) {
                    const float2 rv = *(const float2*)(Rsd + (size_t)z * sR
                                                       + (size_t)r * 1024 + cc);
                    v0 += rv.x; v1 += rv.y;
                }
                if (relu) { v0 = fmaxf(v0, 0.f); v1 = fmaxf(v1, 0.f); }
                if (Cf)
                    *(float2*)(Cf + (size_t)z * sC + (size_t)r * 1024 + cc)
                        = make_float2(v0, v1);
                if (Ch) {
                    if (!trans) {
                        if (Cl) {
                            __half2 h2, l2;
                            split2(v0, v1, h2, l2);
                            *(__half2*)(Ch + (size_t)z * sC + (size_t)r * 1024 + cc) = h2;
                            *(__half2*)(Cl + (size_t)z * sC + (size_t)r * 1024 + cc) = l2;
                        } else {
                            *(__half2*)(Ch + (size_t)z * sC + (size_t)r * 1024 + cc)
                                = __halves2half2(__float2half_rn(v0), __float2half_rn(v1));
                        }
                    } else {
                        const size_t b = (size_t)r >> 10, s5 = (size_t)r & 1023;
                        Ch[((b << 10) + (size_t)cc)     * 1024 + s5] = __float2half_rn(v0);
                        Ch[((b << 10) + (size_t)cc + 1) * 1024 + s5] = __float2half_rn(v1);
                    }
                }
            }
        }
    }
}

// ---------------------------------------------------------------------------
__global__ __launch_bounds__(256) void embed_k(const float* __restrict__ x,
                                               const float* __restrict__ pe,
                                               float* __restrict__ o) {
    size_t i = (size_t)blockIdx.x * 256 + threadIdx.x;
    const float4 a = ((const float4*)x)[i];
    const float4 p = ((const float4*)pe)[i & ((size_t)SEQ * EMB / 4 - 1)];
    ((float4*)o)[i] = make_float4(32.f*a.x+p.x, 32.f*a.y+p.y, 32.f*a.z+p.z, 32.f*a.w+p.w);
}

// weights: hi-only fp16 truncation (B-role)
__global__ __launch_bounds__(256) void splithi_k(const float* __restrict__ in,
                                                 __half* __restrict__ oh) {
    size_t i = ((size_t)blockIdx.x * 256 + threadIdx.x) * 4;
    float4 v = *(const float4*)(in + i);
    *(__half2*)(oh + i)     = __halves2half2(__float2half_rn(v.x), __float2half_rn(v.y));
    *(__half2*)(oh + i + 2) = __halves2half2(__float2half_rn(v.z), __float2half_rn(v.w));
}

__global__ __launch_bounds__(256) void ln_split_k(const float* __restrict__ in,
                                                  const float* __restrict__ g,
                                                  const float* __restrict__ b,
                                                  __half* __restrict__ oh,
                                                  __half* __restrict__ ol) {
    const size_t row = blockIdx.x;
    const int t = threadIdx.x;
    const float4 v = ((const float4*)(in + row * EMB))[t];
    float s  = v.x + v.y + v.z + v.w;
    float ss = v.x*v.x + v.y*v.y + v.z*v.z + v.w*v.w;
#pragma unroll
    for (int o = 16; o > 0; o >>= 1) {
        s  += __shfl_xor_sync(0xFFFFFFFFu, s, o);
        ss += __shfl_xor_sync(0xFFFFFFFFu, ss, o);
    }
    __shared__ float sh_s[8], sh_ss[8];
    if ((t & 31) == 0) { sh_s[t >> 5] = s; sh_ss[t >> 5] = ss; }
    __syncthreads();
    float ts = 0.f, tss = 0.f;
#pragma unroll
    for (int i = 0; i < 8; i++) { ts += sh_s[i]; tss += sh_ss[i]; }
    const float mu  = ts * (1.f / EMB);
    const float inv = rsqrtf(tss * (1.f / EMB) - mu * mu + 1e-5f);
    const float4 gg = ((const float4*)g)[t];
    const float4 bb = ((const float4*)b)[t];
    float r0 = (v.x - mu) * inv * gg.x + bb.x;
    float r1 = (v.y - mu) * inv * gg.y + bb.y;
    float r2 = (v.z - mu) * inv * gg.z + bb.z;
    float r3 = (v.w - mu) * inv * gg.w + bb.w;
    size_t o4 = row * EMB + (size_t)t * 4;
    __half2 h0, l0, h1, l1;
    split2(r0, r1, h0, l0); split2(r2, r3, h1, l1);
    *(__half2*)(oh + o4)     = h0; *(__half2*)(oh + o4 + 2) = h1;
    *(__half2*)(ol + o4)     = l0; *(__half2*)(ol + o4 + 2) = l1;
}

__global__ __launch_bounds__(256) void softmax_k(float* __restrict__ w,
                                                 __half* __restrict__ oh,
                                                 __half* __restrict__ ol) {
    const size_t row = blockIdx.x;
    float4* p = (float4*)(w + row * SEQ);
    const int t = threadIdx.x;
    float4 v = p[t];
    float m = fmaxf(fmaxf(v.x, v.y), fmaxf(v.z, v.w));
#pragma unroll
    for (int o = 16; o > 0; o >>= 1) m = fmaxf(m, __shfl_xor_sync(0xFFFFFFFFu, m, o));
    __shared__ float shm[8], shs[8];
    if ((t & 31) == 0) shm[t >> 5] = m;
    __syncthreads();
    float M = shm[0];
#pragma unroll
    for (int i = 1; i < 8; i++) M = fmaxf(M, shm[i]);
    float4 e;
    e.x = __expf(v.x - M); e.y = __expf(v.y - M);
    e.z = __expf(v.z - M); e.w = __expf(v.w - M);
    float s = e.x + e.y + e.z + e.w;
#pragma unroll
    for (int o = 16; o > 0; o >>= 1) s += __shfl_xor_sync(0xFFFFFFFFu, s, o);
    if ((t & 31) == 0) shs[t >> 5] = s;
    __syncthreads();
    float S = 0.f;
#pragma unroll
    for (int i = 0; i < 8; i++) S += shs[i];
    const float inv = 1.f / S;
    e.x *= inv; e.y *= inv; e.z *= inv; e.w *= inv;
    p[t] = e;
    size_t o4 = row * SEQ + (size_t)t * 4;
    __half2 h0, l0, h1, l1;
    split2(e.x, e.y, h0, l0); split2(e.z, e.w, h1, l1);
    *(__half2*)(oh + o4)     = h0; *(__half2*)(oh + o4 + 2) = h1;
    *(__half2*)(ol + o4)     = l0; *(__half2*)(ol + o4 + 2) = l1;
}

__global__ __launch_bounds__(256) void cls_k(const float* __restrict__ X,
                                             const float* __restrict__ Wc,
                                             const float* __restrict__ bc,
                                             float* __restrict__ out) {
    const int b = blockIdx.x >> 1, o = blockIdx.x & 1;
    const int t = threadIdx.x;
    const float4 a = ((const float4*)(X + (size_t)b * SEQ * EMB))[t];
    const float4 w = ((const float4*)(Wc + (size_t)o * EMB))[t];
    float s = a.x*w.x + a.y*w.y + a.z*w.z + a.w*w.w;
#pragma unroll
    for (int off = 16; off > 0; off >>= 1) s += __shfl_xor_sync(0xFFFFFFFFu, s, off);
    __shared__ float sh[8];
    if ((t & 31) == 0) sh[t >> 5] = s;
    __syncthreads();
    if (t == 0) {
        float S = 0.f;
#pragma unroll
        for (int i = 0; i < 8; i++) S += sh[i];
        out[b * 2 + o] = S + bc[o];
    }
}

// ---------------------------------------------------------------------------
extern "C" void kernel_launch(void* const* d_in, const int* in_sizes, int n_in,
                              void* d_out, int out_size) {
    (void)in_sizes; (void)n_in; (void)out_size;
    const float* x     = (const float*)d_in[0];
    const float* pe    = (const float*)d_in[1];
    const float* ln1_g = (const float*)d_in[2];
    const float* ln1_b = (const float*)d_in[3];
    const float* Wq = (const float*)d_in[4];  const float* bq = (const float*)d_in[5];
    const float* Wk = (const float*)d_in[6];  const float* bk = (const float*)d_in[7];
    const float* Wv = (const float*)d_in[8];  const float* bv = (const float*)d_in[9];
    const float* Wo = (const float*)d_in[10]; const float* bo = (const float*)d_in[11];
    const float* ln2_g = (const float*)d_in[12];
    const float* ln2_b = (const float*)d_in[13];
    const float* W1 = (const float*)d_in[14]; const float* b1 = (const float*)d_in[15];
    const float* W2 = (const float*)d_in[16]; const float* b2 = (const float*)d_in[17];
    const float* Wc = (const float*)d_in[18]; const float* bc = (const float*)d_in[19];

    float* out = (float*)d_out;
    float* w1 = out + 64;
    float* w2 = w1 + NSS;

    float *px, *py;
    __half *hh, *hl, *qh, *ql, *kh, *vh, *wh, *wl, *Wh;
    cudaGetSymbolAddress((void**)&px, g_x);
    cudaGetSymbolAddress((void**)&py, g_y);
    cudaGetSymbolAddress((void**)&hh, g_h_hi);  cudaGetSymbolAddress((void**)&hl, g_h_lo);
    cudaGetSymbolAddress((void**)&qh, g_q_hi);  cudaGetSymbolAddress((void**)&ql, g_q_lo);
    cudaGetSymbolAddress((void**)&kh, g_k_hi);
    cudaGetSymbolAddress((void**)&vh, g_vT_hi);
    cudaGetSymbolAddress((void**)&wh, g_w_hi);  cudaGetSymbolAddress((void**)&wl, g_w_lo);
    cudaGetSymbolAddress((void**)&Wh, g_W_hi);

    cudaFuncSetAttribute(gemm_mma, cudaFuncAttributeMaxDynamicSharedMemorySize, SMEM_DYN);

    const size_t sSE = (size_t)SEQ * EMB;
    const size_t sSS = (size_t)SEQ * SEQ;

    // weight truncation (hi only; B-role)
    const float* Ws[6] = {Wq, Wk, Wv, Wo, W1, W2};
    for (int i = 0; i < 6; i++)
        splithi_k<<<1024, 256>>>(Ws[i], Wh + (size_t)i * WSZ);
    __half *Wqh = Wh,         *Wkh = Wh + WSZ,   *Wvh = Wh + 2*WSZ;
    __half *Woh = Wh + 3*WSZ, *W1h = Wh + 4*WSZ, *W2h = Wh + 5*WSZ;

    // x1 = 32*x + pe
    embed_k<<<(unsigned)(NELEM / 4 / 256), 256>>>(x, pe, px);

    const dim3 gP(EMB / BN, NROWS / BM, 1);     // (8, 256, 1)
    const dim3 gB(SEQ / BN, SEQ / BM, BATCH);   // (8, 8, 32)

    for (int blk = 0; blk < 2; blk++) {
        float* wout = blk ? w2 : w1;
        // h = LN1(x) (hi/lo)
        ln_split_k<<<NROWS, 256>>>(px, ln1_g, ln1_b, hh, hl);
        // q = h@Wq^T + bq (hi/lo: A-role in scores)
        gemm_mma<<<gP, 256, SMEM_DYN>>>(hh, hl, 0, Wqh, 0, bq, nullptr, 0, 1.f, 0,
                                        nullptr, qh, ql, 0, 0);
        // k (hi only: B-role in scores)
        gemm_mma<<<gP, 256, SMEM_DYN>>>(hh, hl, 0, Wkh, 0, bk, nullptr, 0, 1.f, 0,
                                        nullptr, kh, nullptr, 0, 0);
        // v (transposed hi only: B-role in attn)
        gemm_mma<<<gP, 256, SMEM_DYN>>>(hh, hl, 0, Wvh, 0, bv, nullptr, 0, 1.f, 0,
                                        nullptr, vh, nullptr, 1, 0);
        // scores = q k^T / 32 -> fp32 wout (straight into d_out region)
        gemm_mma<<<gB, 256, SMEM_DYN>>>(qh, ql, sSE, kh, sSE, nullptr, nullptr, 0,
                                        0.03125f, 0, wout, nullptr, nullptr, 0, sSS);
        // softmax in place + hi/lo split (A-role in attn)
        softmax_k<<<NROWS, 256>>>(wout, wh, wl);
        // attn = w @ vT^T -> hi/lo into h (A-role for Wo)
        gemm_mma<<<gB, 256, SMEM_DYN>>>(wh, wl, sSS, vh, sSE, nullptr, nullptr, 0,
                                        1.f, 0, nullptr, hh, hl, 0, sSE);
        // x2 = x1 + attn@Wo^T + bo -> fp32 py
        gemm_mma<<<gP, 256, SMEM_DYN>>>(hh, hl, 0, Woh, 0, bo, px, 0, 1.f, 0,
                                        py, nullptr, nullptr, 0, 0);
        // h = LN2(x2) (hi/lo)
        ln_split_k<<<NROWS, 256>>>(py, ln2_g, ln2_b, hh, hl);
        // f1 = relu(h@W1^T + b1) -> hi/lo into q (A-role for ff2)
        gemm_mma<<<gP, 256, SMEM_DYN>>>(hh, hl, 0, W1h, 0, b1, nullptr, 0, 1.f, 1,
                                        nullptr, qh, ql, 0, 0);
        // x3 = x2 + f1@W2^T + b2 -> fp32 px
        gemm_mma<<<gP, 256, SMEM_DYN>>>(qh, ql, 0, W2h, 0, b2, py, 0, 1.f, 0,
                                        px, nullptr, nullptr, 0, 0);
    }

    cls_k<<<64, 256>>>(px, Wc, bc, out);
}

// round 13
// speedup vs baseline: 2.0927x; 1.4222x over previous
#include <cuda_runtime.h>
#include <cuda_fp16.h>

#define EMB   1024
#define SEQ   1024
#define BATCH 32
#define KDIM  1024
#define NROWS (BATCH*SEQ)
#define NELEM ((size_t)NROWS*EMB)
#define NSS   ((size_t)BATCH*SEQ*SEQ)
#define WSZ   ((size_t)1024*1024)

// GEMM tiling
#define BM 128
#define BN 128
#define BK 32
#define NQ  (KDIM/BK)   // 32 K-chunks
#define NST 4           // cp.async pipeline depth
#define LDS 40          // padded smem row stride (elements)

#define TILE_B      (BM*LDS*2)              // 10240 bytes per 128x32 fp16 tile
#define SMEM_NP1    (NST*2*TILE_B)          // 81920  (Ah,Bh per stage)
#define SMEM_NP2    (NST*3*TILE_B)          // 122880 (Ah,Al,Bh per stage)

// ---------------- PTX helpers (portable sm_80+ only) ----------------
__device__ __forceinline__ unsigned smem_u32(const void* p) {
    unsigned a;
    asm("{ .reg .u64 t; cvta.to.shared.u64 t, %1; cvt.u32.u64 %0, t; }" : "=r"(a) : "l"(p));
    return a;
}
#define CPASYNC16(dst, src) \
    asm volatile("cp.async.cg.shared.global [%0], [%1], 16;" :: "r"(dst), "l"(src))
#define CPCOMMIT() asm volatile("cp.async.commit_group;" ::: "memory")
#define CPWAIT(n)  asm volatile("cp.async.wait_group %0;" :: "n"(n) : "memory")
#define LDSM4(r0, r1, r2, r3, a) \
    asm volatile("ldmatrix.sync.aligned.m8n8.x4.shared.b16 {%0,%1,%2,%3}, [%4];" \
        : "=r"(r0), "=r"(r1), "=r"(r2), "=r"(r3) : "r"(a))
#define MMA(c, a, b) \
    asm volatile("mma.sync.aligned.m16n8k16.row.col.f32.f16.f16.f32 " \
        "{%0,%1,%2,%3}, {%4,%5,%6,%7}, {%8,%9}, {%0,%1,%2,%3};" \
        : "+f"((c)[0]), "+f"((c)[1]), "+f"((c)[2]), "+f"((c)[3]) \
        : "r"((a)[0]), "r"((a)[1]), "r"((a)[2]), "r"((a)[3]), "r"((b)[0]), "r"((b)[1]))

__device__ __forceinline__ void split2(float a, float b, __half2& h, __half2& l) {
    __half ha = __float2half_rn(a), hb = __float2half_rn(b);
    h = __halves2half2(ha, hb);
    l = __halves2half2(__float2half_rn(a - __half2float(ha)),
                       __float2half_rn(b - __half2float(hb)));
}

// ---------------- scratch ----------------
__device__ float g_x[NELEM];                       // residual stream (fp32)
__device__ float g_y[NELEM];                       // x2 (fp32)
__device__ __half g_h_hi[NELEM];                   // LN out / attn out (fp16)
__device__ __half g_q_hi[NELEM],  g_q_lo[NELEM];   // q hi/lo (scores A); later f1 (hi)
__device__ __half g_k_hi[NELEM];                   // k
__device__ __half g_vT_hi[NELEM];                  // v transposed
__device__ __half g_w_hi[NSS];                     // softmax weights (fp16)
__device__ __half g_W_hi[6*WSZ];                   // weights (fp16)

// ---------------------------------------------------------------------------
// Tensor-core GEMM: C = alpha*(A @ B^T) [+bias] [+Rsd] [relu]
// NP=1: plain fp16 (A=Ah). NP=2: A = Ah + Al (fp16 hi/lo), C = Ah·Bh + Al·Bh.
// 32 K-chunks, 4-deep cp.async pipeline, 1 barrier/chunk.
// grid = (N/128, M/128, Z). Outputs: fp32 Cf and/or fp16 Ch (+Cl split);
// trans=1 stores C[r,e] at [(b*1024+e)*1024 + s], r = b*1024+s (hi only).
// ---------------------------------------------------------------------------
template<int NP>
__global__ void __launch_bounds__(256, 1) gemm_mma(
    const __half* __restrict__ Ah, const __half* __restrict__ Al, size_t sA,
    const __half* __restrict__ Bh, size_t sB,
    const float* __restrict__ bias,
    const float* __restrict__ Rsd, size_t sR,
    float alpha, int relu,
    float* __restrict__ Cf,
    __half* __restrict__ Ch, __half* __restrict__ Cl,
    int trans, size_t sC)
{
    extern __shared__ __align__(16) char dynsm[];
    const unsigned dynB = smem_u32(dynsm);
    constexpr unsigned STG = (NP + 1) * TILE_B;       // per-stage bytes
    constexpr unsigned OFFB = NP * TILE_B;            // B-tile offset in stage

    const int tid = threadIdx.x, wid = tid >> 5, lane = tid & 31;
    const int wm = wid & 3, wn = wid >> 2;            // warp grid 4(m) x 2(n)
    const int g = lane >> 2, tig = lane & 3;
    const int bm = blockIdx.y * BM, bn = blockIdx.x * BN;
    const int z = blockIdx.z;
    Ah += (size_t)z * sA;
    if (NP == 2) Al += (size_t)z * sA;
    Bh += (size_t)z * sB;

    // staging: thread -> (row, 8-elem col group); 2 iters cover 128 rows
    const int srow = tid >> 2, sc = (tid & 3) * 8;
    // ldmatrix per-thread base offsets (bytes) — validated mapping
    const unsigned aoff0 = (unsigned)((wm * 32 + (lane & 15)) * LDS + (lane >> 4) * 8) * 2;
    const unsigned boff0 = (unsigned)((wn * 64 + (lane >> 4) * 8 + (lane & 7)) * LDS
                                      + ((lane >> 3) & 1) * 8) * 2;

    float acc[2][8][4];
#pragma unroll
    for (int a = 0; a < 2; a++)
#pragma unroll
        for (int b = 0; b < 8; b++)
#pragma unroll
            for (int c = 0; c < 4; c++) acc[a][b][c] = 0.f;

    auto stage = [&](int q, int buf) {
        const int ko = q * BK;
        const unsigned d = dynB + (unsigned)buf * STG;
#pragma unroll
        for (int i = 0; i < 2; i++) {
            const int row = srow + i * 64;
            const unsigned so = (unsigned)(row * LDS + sc) * 2;
            const size_t ga = (size_t)(bm + row) * KDIM + ko + sc;
            const size_t gb = (size_t)(bn + row) * KDIM + ko + sc;
            CPASYNC16(d + so, (const void*)(Ah + ga));
            if (NP == 2) CPASYNC16(d + TILE_B + so, (const void*)(Al + ga));
            CPASYNC16(d + OFFB + so, (const void*)(Bh + gb));
        }
    };

    auto compute = [&](int buf) {
        const unsigned sb = dynB + (unsigned)buf * STG;
#pragma unroll
        for (int ks = 0; ks < 2; ks++) {
            const unsigned kof = (unsigned)(ks * 16) * 2;
            unsigned afh[2][4], afl[2][4];
#pragma unroll
            for (int mi = 0; mi < 2; mi++) {
                const unsigned mof = aoff0 + (unsigned)(mi * 16 * LDS) * 2 + kof;
                LDSM4(afh[mi][0], afh[mi][1], afh[mi][2], afh[mi][3], sb + mof);
                if (NP == 2)
                    LDSM4(afl[mi][0], afl[mi][1], afl[mi][2], afl[mi][3],
                          sb + TILE_B + mof);
            }
            unsigned bfh[8][2];
#pragma unroll
            for (int jp = 0; jp < 4; jp++) {
                const unsigned nof = boff0 + (unsigned)(jp * 16 * LDS) * 2 + kof;
                unsigned r0, r1, r2, r3;
                LDSM4(r0, r1, r2, r3, sb + OFFB + nof);
                bfh[jp*2][0] = r0; bfh[jp*2][1] = r1;
                bfh[jp*2+1][0] = r2; bfh[jp*2+1][1] = r3;
            }
#pragma unroll
            for (int mi = 0; mi < 2; mi++)
#pragma unroll
                for (int ni = 0; ni < 8; ni++)
                    MMA(acc[mi][ni], afh[mi], bfh[ni]);
            if (NP == 2) {
#pragma unroll
                for (int mi = 0; mi < 2; mi++)
#pragma unroll
                    for (int ni = 0; ni < 8; ni++)
                        MMA(acc[mi][ni], afl[mi], bfh[ni]);
            }
        }
    };

    // prologue: prefetch stages 0..NST-2
#pragma unroll
    for (int s = 0; s < NST - 1; s++) { stage(s, s); CPCOMMIT(); }

    for (int q = 0; q < NQ; q++) {
        CPWAIT(NST - 2);
        __syncthreads();
        if (q + NST - 1 < NQ) stage(q + NST - 1, (q + NST - 1) & (NST - 1));
        CPCOMMIT();
        compute(q & (NST - 1));
    }

    // ---- epilogue ----
#pragma unroll
    for (int mi = 0; mi < 2; mi++) {
#pragma unroll
        for (int half = 0; half < 2; half++) {
            const int r = bm + wm * 32 + mi * 16 + g + half * 8;
#pragma unroll
            for (int ni = 0; ni < 8; ni++) {
                const int cc = bn + wn * 64 + ni * 8 + tig * 2;
                float v0 = acc[mi][ni][half * 2 + 0] * alpha;
                float v1 = acc[mi][ni][half * 2 + 1] * alpha;
                if (bias) { v0 += __ldg(bias + cc); v1 += __ldg(bias + cc + 1); }
                if (Rsd) {
                    const float2 rv = *(const float2*)(Rsd + (size_t)z * sR
                                                       + (size_t)r * 1024 + cc);
                    v0 += rv.x; v1 += rv.y;
                }
                if (relu) { v0 = fmaxf(v0, 0.f); v1 = fmaxf(v1, 0.f); }
                if (Cf)
                    *(float2*)(Cf + (size_t)z * sC + (size_t)r * 1024 + cc)
                        = make_float2(v0, v1);
                if (Ch) {
                    if (!trans) {
                        if (Cl) {
                            __half2 h2, l2;
                            split2(v0, v1, h2, l2);
                            *(__half2*)(Ch + (size_t)z * sC + (size_t)r * 1024 + cc) = h2;
                            *(__half2*)(Cl + (size_t)z * sC + (size_t)r * 1024 + cc) = l2;
                        } else {
                            *(__half2*)(Ch + (size_t)z * sC + (size_t)r * 1024 + cc)
                                = __halves2half2(__float2half_rn(v0), __float2half_rn(v1));
                        }
                    } else {
                        const size_t b = (size_t)r >> 10, s5 = (size_t)r & 1023;
                        Ch[((b << 10) + (size_t)cc)     * 1024 + s5] = __float2half_rn(v0);
                        Ch[((b << 10) + (size_t)cc + 1) * 1024 + s5] = __float2half_rn(v1);
                    }
                }
            }
        }
    }
}

// ---------------------------------------------------------------------------
__global__ __launch_bounds__(256) void embed_k(const float* __restrict__ x,
                                               const float* __restrict__ pe,
                                               float* __restrict__ o) {
    size_t i = (size_t)blockIdx.x * 256 + threadIdx.x;
    const float4 a = ((const float4*)x)[i];
    const float4 p = ((const float4*)pe)[i & ((size_t)SEQ * EMB / 4 - 1)];
    ((float4*)o)[i] = make_float4(32.f*a.x+p.x, 32.f*a.y+p.y, 32.f*a.z+p.z, 32.f*a.w+p.w);
}

// fp16 truncation (weights)
__global__ __launch_bounds__(256) void splithi_k(const float* __restrict__ in,
                                                 __half* __restrict__ oh) {
    size_t i = ((size_t)blockIdx.x * 256 + threadIdx.x) * 4;
    float4 v = *(const float4*)(in + i);
    *(__half2*)(oh + i)     = __halves2half2(__float2half_rn(v.x), __float2half_rn(v.y));
    *(__half2*)(oh + i + 2) = __halves2half2(__float2half_rn(v.z), __float2half_rn(v.w));
}

// LayerNorm -> fp16 (hi only)
__global__ __launch_bounds__(256) void ln_hi_k(const float* __restrict__ in,
                                               const float* __restrict__ g,
                                               const float* __restrict__ b,
                                               __half* __restrict__ oh) {
    const size_t row = blockIdx.x;
    const int t = threadIdx.x;
    const float4 v = ((const float4*)(in + row * EMB))[t];
    float s  = v.x + v.y + v.z + v.w;
    float ss = v.x*v.x + v.y*v.y + v.z*v.z + v.w*v.w;
#pragma unroll
    for (int o = 16; o > 0; o >>= 1) {
        s  += __shfl_xor_sync(0xFFFFFFFFu, s, o);
        ss += __shfl_xor_sync(0xFFFFFFFFu, ss, o);
    }
    __shared__ float sh_s[8], sh_ss[8];
    if ((t & 31) == 0) { sh_s[t >> 5] = s; sh_ss[t >> 5] = ss; }
    __syncthreads();
    float ts = 0.f, tss = 0.f;
#pragma unroll
    for (int i = 0; i < 8; i++) { ts += sh_s[i]; tss += sh_ss[i]; }
    const float mu  = ts * (1.f / EMB);
    const float inv = rsqrtf(tss * (1.f / EMB) - mu * mu + 1e-5f);
    const float4 gg = ((const float4*)g)[t];
    const float4 bb = ((const float4*)b)[t];
    float r0 = (v.x - mu) * inv * gg.x + bb.x;
    float r1 = (v.y - mu) * inv * gg.y + bb.y;
    float r2 = (v.z - mu) * inv * gg.z + bb.z;
    float r3 = (v.w - mu) * inv * gg.w + bb.w;
    size_t o4 = row * EMB + (size_t)t * 4;
    *(__half2*)(oh + o4)     = __halves2half2(__float2half_rn(r0), __float2half_rn(r1));
    *(__half2*)(oh + o4 + 2) = __halves2half2(__float2half_rn(r2), __float2half_rn(r3));
}

// softmax in place (fp32) + fp16 hi output
__global__ __launch_bounds__(256) void softmax_k(float* __restrict__ w,
                                                 __half* __restrict__ oh) {
    const size_t row = blockIdx.x;
    float4* p = (float4*)(w + row * SEQ);
    const int t = threadIdx.x;
    float4 v = p[t];
    float m = fmaxf(fmaxf(v.x, v.y), fmaxf(v.z, v.w));
#pragma unroll
    for (int o = 16; o > 0; o >>= 1) m = fmaxf(m, __shfl_xor_sync(0xFFFFFFFFu, m, o));
    __shared__ float shm[8], shs[8];
    if ((t & 31) == 0) shm[t >> 5] = m;
    __syncthreads();
    float M = shm[0];
#pragma unroll
    for (int i = 1; i < 8; i++) M = fmaxf(M, shm[i]);
    float4 e;
    e.x = __expf(v.x - M); e.y = __expf(v.y - M);
    e.z = __expf(v.z - M); e.w = __expf(v.w - M);
    float s = e.x + e.y + e.z + e.w;
#pragma unroll
    for (int o = 16; o > 0; o >>= 1) s += __shfl_xor_sync(0xFFFFFFFFu, s, o);
    if ((t & 31) == 0) shs[t >> 5] = s;
    __syncthreads();
    float S = 0.f;
#pragma unroll
    for (int i = 0; i < 8; i++) S += shs[i];
    const float inv = 1.f / S;
    e.x *= inv; e.y *= inv; e.z *= inv; e.w *= inv;
    p[t] = e;
    size_t o4 = row * SEQ + (size_t)t * 4;
    *(__half2*)(oh + o4)     = __halves2half2(__float2half_rn(e.x), __float2half_rn(e.y));
    *(__half2*)(oh + o4 + 2) = __halves2half2(__float2half_rn(e.z), __float2half_rn(e.w));
}

__global__ __launch_bounds__(256) void cls_k(const float* __restrict__ X,
                                             const float* __restrict__ Wc,
                                             const float* __restrict__ bc,
                                             float* __restrict__ out) {
    const int b = blockIdx.x >> 1, o = blockIdx.x & 1;
    const int t = threadIdx.x;
    const float4 a = ((const float4*)(X + (size_t)b * SEQ * EMB))[t];
    const float4 w = ((const float4*)(Wc + (size_t)o * EMB))[t];
    float s = a.x*w.x + a.y*w.y + a.z*w.z + a.w*w.w;
#pragma unroll
    for (int off = 16; off > 0; off >>= 1) s += __shfl_xor_sync(0xFFFFFFFFu, s, off);
    __shared__ float sh[8];
    if ((t & 31) == 0) sh[t >> 5] = s;
    __syncthreads();
    if (t == 0) {
        float S = 0.f;
#pragma unroll
        for (int i = 0; i < 8; i++) S += sh[i];
        out[b * 2 + o] = S + bc[o];
    }
}

// ---------------------------------------------------------------------------
extern "C" void kernel_launch(void* const* d_in, const int* in_sizes, int n_in,
                              void* d_out, int out_size) {
    (void)in_sizes; (void)n_in; (void)out_size;
    const float* x     = (const float*)d_in[0];
    const float* pe    = (const float*)d_in[1];
    const float* ln1_g = (const float*)d_in[2];
    const float* ln1_b = (const float*)d_in[3];
    const float* Wq = (const float*)d_in[4];  const float* bq = (const float*)d_in[5];
    const float* Wk = (const float*)d_in[6];  const float* bk = (const float*)d_in[7];
    const float* Wv = (const float*)d_in[8];  const float* bv = (const float*)d_in[9];
    const float* Wo = (const float*)d_in[10]; const float* bo = (const float*)d_in[11];
    const float* ln2_g = (const float*)d_in[12];
    const float* ln2_b = (const float*)d_in[13];
    const float* W1 = (const float*)d_in[14]; const float* b1 = (const float*)d_in[15];
    const float* W2 = (const float*)d_in[16]; const float* b2 = (const float*)d_in[17];
    const float* Wc = (const float*)d_in[18]; const float* bc = (const float*)d_in[19];

    float* out = (float*)d_out;
    float* w1 = out + 64;
    float* w2 = w1 + NSS;

    float *px, *py;
    __half *hh, *qh, *ql, *kh, *vh, *wh, *Wh;
    cudaGetSymbolAddress((void**)&px, g_x);
    cudaGetSymbolAddress((void**)&py, g_y);
    cudaGetSymbolAddress((void**)&hh, g_h_hi);
    cudaGetSymbolAddress((void**)&qh, g_q_hi);  cudaGetSymbolAddress((void**)&ql, g_q_lo);
    cudaGetSymbolAddress((void**)&kh, g_k_hi);
    cudaGetSymbolAddress((void**)&vh, g_vT_hi);
    cudaGetSymbolAddress((void**)&wh, g_w_hi);
    cudaGetSymbolAddress((void**)&Wh, g_W_hi);

    cudaFuncSetAttribute(gemm_mma<1>, cudaFuncAttributeMaxDynamicSharedMemorySize, SMEM_NP1);
    cudaFuncSetAttribute(gemm_mma<2>, cudaFuncAttributeMaxDynamicSharedMemorySize, SMEM_NP2);

    const size_t sSE = (size_t)SEQ * EMB;
    const size_t sSS = (size_t)SEQ * SEQ;

    // weight truncation
    const float* Ws[6] = {Wq, Wk, Wv, Wo, W1, W2};
    for (int i = 0; i < 6; i++)
        splithi_k<<<1024, 256>>>(Ws[i], Wh + (size_t)i * WSZ);
    __half *Wqh = Wh,         *Wkh = Wh + WSZ,   *Wvh = Wh + 2*WSZ;
    __half *Woh = Wh + 3*WSZ, *W1h = Wh + 4*WSZ, *W2h = Wh + 5*WSZ;

    // x1 = 32*x + pe
    embed_k<<<(unsigned)(NELEM / 4 / 256), 256>>>(x, pe, px);

    const dim3 gP(EMB / BN, NROWS / BM, 1);     // (8, 256, 1)
    const dim3 gB(SEQ / BN, SEQ / BM, BATCH);   // (8, 8, 32)

    for (int blk = 0; blk < 2; blk++) {
        float* wout = blk ? w2 : w1;
        // h = LN1(x) -> fp16
        ln_hi_k<<<NROWS, 256>>>(px, ln1_g, ln1_b, hh);
        // q = h@Wq^T + bq -> hi/lo split (scores A operand)
        gemm_mma<1><<<gP, 256, SMEM_NP1>>>(hh, nullptr, 0, Wqh, 0, bq, nullptr, 0,
                                           1.f, 0, nullptr, qh, ql, 0, 0);
        // k -> fp16
        gemm_mma<1><<<gP, 256, SMEM_NP1>>>(hh, nullptr, 0, Wkh, 0, bk, nullptr, 0,
                                           1.f, 0, nullptr, kh, nullptr, 0, 0);
        // v -> fp16 transposed (attn B operand)
        gemm_mma<1><<<gP, 256, SMEM_NP1>>>(hh, nullptr, 0, Wvh, 0, bv, nullptr, 0,
                                           1.f, 0, nullptr, vh, nullptr, 1, 0);
        // scores = q k^T / 32 -> fp32 wout (2-product: q hi/lo)
        gemm_mma<2><<<gB, 256, SMEM_NP2>>>(qh, ql, sSE, kh, sSE, nullptr, nullptr, 0,
                                           0.03125f, 0, wout, nullptr, nullptr, 0, sSS);
        // softmax in place + fp16
        softmax_k<<<NROWS, 256>>>(wout, wh);
        // attn = w @ vT^T -> fp16 into h (reuse)
        gemm_mma<1><<<gB, 256, SMEM_NP1>>>(wh, nullptr, sSS, vh, sSE, nullptr, nullptr, 0,
                                           1.f, 0, nullptr, hh, nullptr, 0, sSE);
        // x2 = x1 + attn@Wo^T + bo -> fp32 py
        gemm_mma<1><<<gP, 256, SMEM_NP1>>>(hh, nullptr, 0, Woh, 0, bo, px, 0,
                                           1.f, 0, py, nullptr, nullptr, 0, 0);
        // h = LN2(x2) -> fp16
        ln_hi_k<<<NROWS, 256>>>(py, ln2_g, ln2_b, hh);
        // f1 = relu(h@W1^T + b1) -> fp16 into q (reuse, hi only)
        gemm_mma<1><<<gP, 256, SMEM_NP1>>>(hh, nullptr, 0, W1h, 0, b1, nullptr, 0,
                                           1.f, 1, nullptr, qh, nullptr, 0, 0);
        // x3 = x2 + f1@W2^T + b2 -> fp32 px
        gemm_mma<1><<<gP, 256, SMEM_NP1>>>(qh, nullptr, 0, W2h, 0, b2, py, 0,
                                           1.f, 0, px, nullptr, nullptr, 0, 0);
    }

    cls_k<<<64, 256>>>(px, Wc, bc, out);
}

// round 15
// speedup vs baseline: 2.7060x; 1.2930x over previous
#include <cuda_runtime.h>
#include <cuda_fp16.h>

#define EMB   1024
#define SEQ   1024
#define BATCH 32
#define KDIM  1024
#define NROWS (BATCH*SEQ)
#define NELEM ((size_t)NROWS*EMB)
#define NSS   ((size_t)BATCH*SEQ*SEQ)
#define WSZ   ((size_t)1024*1024)

// GEMM tiling
#define BM 128
#define BN 128
#define BK 32
#define NQ  (KDIM/BK)   // 32 K-chunks
#define LDS 40          // padded smem row stride (elements)

#define TILE_B      (BM*LDS*2)              // 10240 bytes per 128x32 fp16 tile
#define NST1 4                              // NP=1 pipeline depth
#define NST2 2                              // NP=2 pipeline depth
#define SMEM_NP1    (NST1*2*TILE_B)         // 81920  -> 2 CTAs/SM
#define SMEM_NP2    (NST2*3*TILE_B)         // 61440  -> 2 CTAs/SM
// trans-epilogue transpose buffer: 128 x (128+8) halves = 34816 B (< SMEM_NP1)
#define TLDS 136

// ---------------- PTX helpers (portable sm_80+ only) ----------------
__device__ __forceinline__ unsigned smem_u32(const void* p) {
    unsigned a;
    asm("{ .reg .u64 t; cvta.to.shared.u64 t, %1; cvt.u32.u64 %0, t; }" : "=r"(a) : "l"(p));
    return a;
}
#define CPASYNC16(dst, src) \
    asm volatile("cp.async.cg.shared.global [%0], [%1], 16;" :: "r"(dst), "l"(src))
#define CPCOMMIT() asm volatile("cp.async.commit_group;" ::: "memory")
#define CPWAIT(n)  asm volatile("cp.async.wait_group %0;" :: "n"(n) : "memory")
#define LDSM4(r0, r1, r2, r3, a) \
    asm volatile("ldmatrix.sync.aligned.m8n8.x4.shared.b16 {%0,%1,%2,%3}, [%4];" \
        : "=r"(r0), "=r"(r1), "=r"(r2), "=r"(r3) : "r"(a))
#define MMA(c, a, b) \
    asm volatile("mma.sync.aligned.m16n8k16.row.col.f32.f16.f16.f32 " \
        "{%0,%1,%2,%3}, {%4,%5,%6,%7}, {%8,%9}, {%0,%1,%2,%3};" \
        : "+f"((c)[0]), "+f"((c)[1]), "+f"((c)[2]), "+f"((c)[3]) \
        : "r"((a)[0]), "r"((a)[1]), "r"((a)[2]), "r"((a)[3]), "r"((b)[0]), "r"((b)[1]))

__device__ __forceinline__ void split2(float a, float b, __half2& h, __half2& l) {
    __half ha = __float2half_rn(a), hb = __float2half_rn(b);
    h = __halves2half2(ha, hb);
    l = __halves2half2(__float2half_rn(a - __half2float(ha)),
                       __float2half_rn(b - __half2float(hb)));
}

// ---------------- scratch ----------------
__device__ float g_x[NELEM];                       // residual stream (fp32)
__device__ float g_y[NELEM];                       // x2 (fp32)
__device__ __half g_h_hi[NELEM];                   // LN out / attn out (fp16)
__device__ __half g_q_hi[NELEM],  g_q_lo[NELEM];   // q hi/lo (scores A); later f1 (hi)
__device__ __half g_k_hi[NELEM];                   // k
__device__ __half g_vT_hi[NELEM];                  // v transposed
__device__ __half g_w_hi[NSS];                     // softmax weights (fp16)
__device__ __half g_W_hi[6*WSZ];                   // weights (fp16)

// ---------------------------------------------------------------------------
// Tensor-core GEMM: C = alpha*(A @ B^T) [+bias] [+Rsd] [relu]
// NP=1: plain fp16. NP=2: A = Ah + Al (fp16 hi/lo), C = Ah·Bh + Al·Bh.
// NQ K-chunks, NST-deep cp.async pipeline, 1 barrier/chunk, 2 CTAs/SM.
// grid = (N/128, M/128, Z). Outputs: fp32 Cf and/or fp16 Ch (+Cl split);
// trans=1 stores C[r,e] at [(b*1024+e)*1024 + s] via smem transpose.
// ---------------------------------------------------------------------------
template<int NP, int NST>
__global__ void __launch_bounds__(256, 2) gemm_mma(
    const __half* __restrict__ Ah, const __half* __restrict__ Al, size_t sA,
    const __half* __restrict__ Bh, size_t sB,
    const float* __restrict__ bias,
    const float* __restrict__ Rsd, size_t sR,
    float alpha, int relu,
    float* __restrict__ Cf,
    __half* __restrict__ Ch, __half* __restrict__ Cl,
    int trans, size_t sC)
{
    extern __shared__ __align__(16) char dynsm[];
    const unsigned dynB = smem_u32(dynsm);
    constexpr unsigned STG = (NP + 1) * TILE_B;       // per-stage bytes
    constexpr unsigned OFFB = NP * TILE_B;            // B-tile offset in stage

    const int tid = threadIdx.x, wid = tid >> 5, lane = tid & 31;
    const int wm = wid & 3, wn = wid >> 2;            // warp grid 4(m) x 2(n)
    const int g = lane >> 2, tig = lane & 3;
    const int bm = blockIdx.y * BM, bn = blockIdx.x * BN;
    const int z = blockIdx.z;
    Ah += (size_t)z * sA;
    if (NP == 2) Al += (size_t)z * sA;
    Bh += (size_t)z * sB;

    // staging: thread -> (row, 8-elem col group); 2 iters cover 128 rows
    const int srow = tid >> 2, sc = (tid & 3) * 8;
    // ldmatrix per-thread base offsets (bytes) — validated mapping
    const unsigned aoff0 = (unsigned)((wm * 32 + (lane & 15)) * LDS + (lane >> 4) * 8) * 2;
    const unsigned boff0 = (unsigned)((wn * 64 + (lane >> 4) * 8 + (lane & 7)) * LDS
                                      + ((lane >> 3) & 1) * 8) * 2;

    float acc[2][8][4];
#pragma unroll
    for (int a = 0; a < 2; a++)
#pragma unroll
        for (int b = 0; b < 8; b++)
#pragma unroll
            for (int c = 0; c < 4; c++) acc[a][b][c] = 0.f;

    auto stage = [&](int q, int buf) {
        const int ko = q * BK;
        const unsigned d = dynB + (unsigned)buf * STG;
#pragma unroll
        for (int i = 0; i < 2; i++) {
            const int row = srow + i * 64;
            const unsigned so = (unsigned)(row * LDS + sc) * 2;
            const size_t ga = (size_t)(bm + row) * KDIM + ko + sc;
            const size_t gb = (size_t)(bn + row) * KDIM + ko + sc;
            CPASYNC16(d + so, (const void*)(Ah + ga));
            if (NP == 2) CPASYNC16(d + TILE_B + so, (const void*)(Al + ga));
            CPASYNC16(d + OFFB + so, (const void*)(Bh + gb));
        }
    };

    auto compute = [&](int buf) {
        const unsigned sb = dynB + (unsigned)buf * STG;
#pragma unroll
        for (int ks = 0; ks < 2; ks++) {
            const unsigned kof = (unsigned)(ks * 16) * 2;
            unsigned afh[2][4], afl[2][4];
#pragma unroll
            for (int mi = 0; mi < 2; mi++) {
                const unsigned mof = aoff0 + (unsigned)(mi * 16 * LDS) * 2 + kof;
                LDSM4(afh[mi][0], afh[mi][1], afh[mi][2], afh[mi][3], sb + mof);
                if (NP == 2)
                    LDSM4(afl[mi][0], afl[mi][1], afl[mi][2], afl[mi][3],
                          sb + TILE_B + mof);
            }
            unsigned bfh[8][2];
#pragma unroll
            for (int jp = 0; jp < 4; jp++) {
                const unsigned nof = boff0 + (unsigned)(jp * 16 * LDS) * 2 + kof;
                unsigned r0, r1, r2, r3;
                LDSM4(r0, r1, r2, r3, sb + OFFB + nof);
                bfh[jp*2][0] = r0; bfh[jp*2][1] = r1;
                bfh[jp*2+1][0] = r2; bfh[jp*2+1][1] = r3;
            }
#pragma unroll
            for (int mi = 0; mi < 2; mi++)
#pragma unroll
                for (int ni = 0; ni < 8; ni++)
                    MMA(acc[mi][ni], afh[mi], bfh[ni]);
            if (NP == 2) {
#pragma unroll
                for (int mi = 0; mi < 2; mi++)
#pragma unroll
                    for (int ni = 0; ni < 8; ni++)
                        MMA(acc[mi][ni], afl[mi], bfh[ni]);
            }
        }
    };

    // prologue: prefetch stages 0..NST-2
#pragma unroll
    for (int s = 0; s < NST - 1; s++) { stage(s, s); CPCOMMIT(); }

    for (int q = 0; q < NQ; q++) {
        CPWAIT(NST - 2);
        __syncthreads();
        if (q + NST - 1 < NQ) stage(q + NST - 1, (q + NST - 1) & (NST - 1));
        CPCOMMIT();
        compute(q & (NST - 1));
    }

    // ---- epilogue ----
    if (Ch && trans) {
        // smem transpose -> coalesced stores along s
        __syncthreads();
        __half* ts = (__half*)dynsm;    // [128 cols e][TLDS] layout
#pragma unroll
        for (int mi = 0; mi < 2; mi++)
#pragma unroll
            for (int half = 0; half < 2; half++) {
                const int rl = wm * 32 + mi * 16 + g + half * 8;   // tile-local row (s)
#pragma unroll
                for (int ni = 0; ni < 8; ni++) {
                    const int cl = wn * 64 + ni * 8 + tig * 2;     // tile-local col (e)
                    ts[(cl)     * TLDS + rl] = __float2half_rn(acc[mi][ni][half*2+0] * alpha
                                               + (bias ? __ldg(bias + bn + cl)     : 0.f));
                    ts[(cl + 1) * TLDS + rl] = __float2half_rn(acc[mi][ni][half*2+1] * alpha
                                               + (bias ? __ldg(bias + bn + cl + 1) : 0.f));
                }
            }
        __syncthreads();
        // r = bm + s_local; whole tile lies in one batch b
        const size_t b = (size_t)bm >> 10, s0 = (size_t)bm & 1023;
        const int col = tid >> 1, hhalf = (tid & 1) * 64;          // 128 cols x 2 halves
        __half* dst = Ch + ((b << 10) + (size_t)(bn + col)) * 1024 + s0 + hhalf;
        const __half* src = ts + col * TLDS + hhalf;
#pragma unroll
        for (int j = 0; j < 8; j++)
            *(uint4*)(dst + j * 8) = *(const uint4*)(src + j * 8);
        return;
    }

#pragma unroll
    for (int mi = 0; mi < 2; mi++) {
#pragma unroll
        for (int half = 0; half < 2; half++) {
            const int r = bm + wm * 32 + mi * 16 + g + half * 8;
#pragma unroll
            for (int ni = 0; ni < 8; ni++) {
                const int cc = bn + wn * 64 + ni * 8 + tig * 2;
                float v0 = acc[mi][ni][half * 2 + 0] * alpha;
                float v1 = acc[mi][ni][half * 2 + 1] * alpha;
                if (bias) { v0 += __ldg(bias + cc); v1 += __ldg(bias + cc + 1); }
                if (Rsd) {
                    const float2 rv = *(const float2*)(Rsd + (size_t)z * sR
                                                       + (size_t)r * 1024 + cc);
                    v0 += rv.x; v1 += rv.y;
                }
                if (relu) { v0 = fmaxf(v0, 0.f); v1 = fmaxf(v1, 0.f); }
                if (Cf)
                    *(float2*)(Cf + (size_t)z * sC + (size_t)r * 1024 + cc)
                        = make_float2(v0, v1);
                if (Ch) {
                    if (Cl) {
                        __half2 h2, l2;
                        split2(v0, v1, h2, l2);
                        *(__half2*)(Ch + (size_t)z * sC + (size_t)r * 1024 + cc) = h2;
                        *(__half2*)(Cl + (size_t)z * sC + (size_t)r * 1024 + cc) = l2;
                    } else {
                        *(__half2*)(Ch + (size_t)z * sC + (size_t)r * 1024 + cc)
                            = __halves2half2(__float2half_rn(v0), __float2half_rn(v1));
                    }
                }
            }
        }
    }
}

// ---------------------------------------------------------------------------
__global__ __launch_bounds__(256) void embed_k(const float* __restrict__ x,
                                               const float* __restrict__ pe,
                                               float* __restrict__ o) {
    size_t i = (size_t)blockIdx.x * 256 + threadIdx.x;
    const float4 a = ((const float4*)x)[i];
    const float4 p = ((const float4*)pe)[i & ((size_t)SEQ * EMB / 4 - 1)];
    ((float4*)o)[i] = make_float4(32.f*a.x+p.x, 32.f*a.y+p.y, 32.f*a.z+p.z, 32.f*a.w+p.w);
}

// fp16 truncation (weights)
__global__ __launch_bounds__(256) void splithi_k(const float* __restrict__ in,
                                                 __half* __restrict__ oh) {
    size_t i = ((size_t)blockIdx.x * 256 + threadIdx.x) * 4;
    float4 v = *(const float4*)(in + i);
    *(__half2*)(oh + i)     = __halves2half2(__float2half_rn(v.x), __float2half_rn(v.y));
    *(__half2*)(oh + i + 2) = __halves2half2(__float2half_rn(v.z), __float2half_rn(v.w));
}

// LayerNorm -> fp16 (hi only)
__global__ __launch_bounds__(256) void ln_hi_k(const float* __restrict__ in,
                                               const float* __restrict__ g,
                                               const float* __restrict__ b,
                                               __half* __restrict__ oh) {
    const size_t row = blockIdx.x;
    const int t = threadIdx.x;
    const float4 v = ((const float4*)(in + row * EMB))[t];
    float s  = v.x + v.y + v.z + v.w;
    float ss = v.x*v.x + v.y*v.y + v.z*v.z + v.w*v.w;
#pragma unroll
    for (int o = 16; o > 0; o >>= 1) {
        s  += __shfl_xor_sync(0xFFFFFFFFu, s, o);
        ss += __shfl_xor_sync(0xFFFFFFFFu, ss, o);
    }
    __shared__ float sh_s[8], sh_ss[8];
    if ((t & 31) == 0) { sh_s[t >> 5] = s; sh_ss[t >> 5] = ss; }
    __syncthreads();
    float ts = 0.f, tss = 0.f;
#pragma unroll
    for (int i = 0; i < 8; i++) { ts += sh_s[i]; tss += sh_ss[i]; }
    const float mu  = ts * (1.f / EMB);
    const float inv = rsqrtf(tss * (1.f / EMB) - mu * mu + 1e-5f);
    const float4 gg = ((const float4*)g)[t];
    const float4 bb = ((const float4*)b)[t];
    float r0 = (v.x - mu) * inv * gg.x + bb.x;
    float r1 = (v.y - mu) * inv * gg.y + bb.y;
    float r2 = (v.z - mu) * inv * gg.z + bb.z;
    float r3 = (v.w - mu) * inv * gg.w + bb.w;
    size_t o4 = row * EMB + (size_t)t * 4;
    *(__half2*)(oh + o4)     = __halves2half2(__float2half_rn(r0), __float2half_rn(r1));
    *(__half2*)(oh + o4 + 2) = __halves2half2(__float2half_rn(r2), __float2half_rn(r3));
}

// softmax in place (fp32) + fp16 hi output
__global__ __launch_bounds__(256) void softmax_k(float* __restrict__ w,
                                                 __half* __restrict__ oh) {
    const size_t row = blockIdx.x;
    float4* p = (float4*)(w + row * SEQ);
    const int t = threadIdx.x;
    float4 v = p[t];
    float m = fmaxf(fmaxf(v.x, v.y), fmaxf(v.z, v.w));
#pragma unroll
    for (int o = 16; o > 0; o >>= 1) m = fmaxf(m, __shfl_xor_sync(0xFFFFFFFFu, m, o));
    __shared__ float shm[8], shs[8];
    if ((t & 31) == 0) shm[t >> 5] = m;
    __syncthreads();
    float M = shm[0];
#pragma unroll
    for (int i = 1; i < 8; i++) M = fmaxf(M, shm[i]);
    float4 e;
    e.x = __expf(v.x - M); e.y = __expf(v.y - M);
    e.z = __expf(v.z - M); e.w = __expf(v.w - M);
    float s = e.x + e.y + e.z + e.w;
#pragma unroll
    for (int o = 16; o > 0; o >>= 1) s += __shfl_xor_sync(0xFFFFFFFFu, s, o);
    if ((t & 31) == 0) shs[t >> 5] = s;
    __syncthreads();
    float S = 0.f;
#pragma unroll
    for (int i = 0; i < 8; i++) S += shs[i];
    const float inv = 1.f / S;
    e.x *= inv; e.y *= inv; e.z *= inv; e.w *= inv;
    p[t] = e;
    size_t o4 = row * SEQ + (size_t)t * 4;
    *(__half2*)(oh + o4)     = __halves2half2(__float2half_rn(e.x), __float2half_rn(e.y));
    *(__half2*)(oh + o4 + 2) = __halves2half2(__float2half_rn(e.z), __float2half_rn(e.w));
}

__global__ __launch_bounds__(256) void cls_k(const float* __restrict__ X,
                                             const float* __restrict__ Wc,
                                             const float* __restrict__ bc,
                                             float* __restrict__ out) {
    const int b = blockIdx.x >> 1, o = blockIdx.x & 1;
    const int t = threadIdx.x;
    const float4 a = ((const float4*)(X + (size_t)b * SEQ * EMB))[t];
    const float4 w = ((const float4*)(Wc + (size_t)o * EMB))[t];
    float s = a.x*w.x + a.y*w.y + a.z*w.z + a.w*w.w;
#pragma unroll
    for (int off = 16; off > 0; off >>= 1) s += __shfl_xor_sync(0xFFFFFFFFu, s, off);
    __shared__ float sh[8];
    if ((t & 31) == 0) sh[t >> 5] = s;
    __syncthreads();
    if (t == 0) {
        float S = 0.f;
#pragma unroll
        for (int i = 0; i < 8; i++) S += sh[i];
        out[b * 2 + o] = S + bc[o];
    }
}

// ---------------------------------------------------------------------------
extern "C" void kernel_launch(void* const* d_in, const int* in_sizes, int n_in,
                              void* d_out, int out_size) {
    (void)in_sizes; (void)n_in; (void)out_size;
    const float* x     = (const float*)d_in[0];
    const float* pe    = (const float*)d_in[1];
    const float* ln1_g = (const float*)d_in[2];
    const float* ln1_b = (const float*)d_in[3];
    const float* Wq = (const float*)d_in[4];  const float* bq = (const float*)d_in[5];
    const float* Wk = (const float*)d_in[6];  const float* bk = (const float*)d_in[7];
    const float* Wv = (const float*)d_in[8];  const float* bv = (const float*)d_in[9];
    const float* Wo = (const float*)d_in[10]; const float* bo = (const float*)d_in[11];
    const float* ln2_g = (const float*)d_in[12];
    const float* ln2_b = (const float*)d_in[13];
    const float* W1 = (const float*)d_in[14]; const float* b1 = (const float*)d_in[15];
    const float* W2 = (const float*)d_in[16]; const float* b2 = (const float*)d_in[17];
    const float* Wc = (const float*)d_in[18]; const float* bc = (const float*)d_in[19];

    float* out = (float*)d_out;
    float* w1 = out + 64;
    float* w2 = w1 + NSS;

    float *px, *py;
    __half *hh, *qh, *ql, *kh, *vh, *wh, *Wh;
    cudaGetSymbolAddress((void**)&px, g_x);
    cudaGetSymbolAddress((void**)&py, g_y);
    cudaGetSymbolAddress((void**)&hh, g_h_hi);
    cudaGetSymbolAddress((void**)&qh, g_q_hi);  cudaGetSymbolAddress((void**)&ql, g_q_lo);
    cudaGetSymbolAddress((void**)&kh, g_k_hi);
    cudaGetSymbolAddress((void**)&vh, g_vT_hi);
    cudaGetSymbolAddress((void**)&wh, g_w_hi);
    cudaGetSymbolAddress((void**)&Wh, g_W_hi);

    cudaFuncSetAttribute(gemm_mma<1, NST1>, cudaFuncAttributeMaxDynamicSharedMemorySize, SMEM_NP1);
    cudaFuncSetAttribute(gemm_mma<2, NST2>, cudaFuncAttributeMaxDynamicSharedMemorySize, SMEM_NP2);
    cudaFuncSetAttribute(gemm_mma<1, NST1>, cudaFuncAttributePreferredSharedMemoryCarveout, 100);
    cudaFuncSetAttribute(gemm_mma<2, NST2>, cudaFuncAttributePreferredSharedMemoryCarveout, 100);

    const size_t sSE = (size_t)SEQ * EMB;
    const size_t sSS = (size_t)SEQ * SEQ;

    // weight truncation
    const float* Ws[6] = {Wq, Wk, Wv, Wo, W1, W2};
    for (int i = 0; i < 6; i++)
        splithi_k<<<1024, 256>>>(Ws[i], Wh + (size_t)i * WSZ);
    __half *Wqh = Wh,         *Wkh = Wh + WSZ,   *Wvh = Wh + 2*WSZ;
    __half *Woh = Wh + 3*WSZ, *W1h = Wh + 4*WSZ, *W2h = Wh + 5*WSZ;

    // x1 = 32*x + pe
    embed_k<<<(unsigned)(NELEM / 4 / 256), 256>>>(x, pe, px);

    const dim3 gP(EMB / BN, NROWS / BM, 1);     // (8, 256, 1)
    const dim3 gB(SEQ / BN, SEQ / BM, BATCH);   // (8, 8, 32)

    for (int blk = 0; blk < 2; blk++) {
        float* wout = blk ? w2 : w1;
        // h = LN1(x) -> fp16
        ln_hi_k<<<NROWS, 256>>>(px, ln1_g, ln1_b, hh);
        // q = h@Wq^T + bq -> hi/lo split (scores A operand)
        gemm_mma<1, NST1><<<gP, 256, SMEM_NP1>>>(hh, nullptr, 0, Wqh, 0, bq, nullptr, 0,
                                                 1.f, 0, nullptr, qh, ql, 0, 0);
        // k -> fp16
        gemm_mma<1, NST1><<<gP, 256, SMEM_NP1>>>(hh, nullptr, 0, Wkh, 0, bk, nullptr, 0,
                                                 1.f, 0, nullptr, kh, nullptr, 0, 0);
        // v -> fp16 transposed (attn B operand)
        gemm_mma<1, NST1><<<gP, 256, SMEM_NP1>>>(hh, nullptr, 0, Wvh, 0, bv, nullptr, 0,
                                                 1.f, 0, nullptr, vh, nullptr, 1, 0);
        // scores = q k^T / 32 -> fp32 wout (2-product: q hi/lo)
        gemm_mma<2, NST2><<<gB, 256, SMEM_NP2>>>(qh, ql, sSE, kh, sSE, nullptr, nullptr, 0,
                                                 0.03125f, 0, wout, nullptr, nullptr, 0, sSS);
        // softmax in place + fp16
        softmax_k<<<NROWS, 256>>>(wout, wh);
        // attn = w @ vT^T -> fp16 into h (reuse)
        gemm_mma<1, NST1><<<gB, 256, SMEM_NP1>>>(wh, nullptr, sSS, vh, sSE, nullptr, nullptr, 0,
                                                 1.f, 0, nullptr, hh, nullptr, 0, sSE);
        // x2 = x1 + attn@Wo^T + bo -> fp32 py
        gemm_mma<1, NST1><<<gP, 256, SMEM_NP1>>>(hh, nullptr, 0, Woh, 0, bo, px, 0,
                                                 1.f, 0, py, nullptr, nullptr, 0, 0);
        // h = LN2(x2) -> fp16
        ln_hi_k<<<NROWS, 256>>>(py, ln2_g, ln2_b, hh);
        // f1 = relu(h@W1^T + b1) -> fp16 into q (reuse, hi only)
        gemm_mma<1, NST1><<<gP, 256, SMEM_NP1>>>(hh, nullptr, 0, W1h, 0, b1, nullptr, 0,
                                                 1.f, 1, nullptr, qh, nullptr, 0, 0);
        // x3 = x2 + f1@W2^T + b2 -> fp32 px
        gemm_mma<1, NST1><<<gP, 256, SMEM_NP1>>>(qh, nullptr, 0, W2h, 0, b2, py, 0,
                                                 1.f, 0, px, nullptr, nullptr, 0, 0);
    }

    cls_k<<<64, 256>>>(px, Wc, bc, out);
}

// round 17
// speedup vs baseline: 3.1072x; 1.1483x over previous
#include <cuda_runtime.h>
#include <cuda_fp16.h>

#define EMB   1024
#define SEQ   1024
#define BATCH 32
#define KDIM  1024
#define NROWS (BATCH*SEQ)
#define NELEM ((size_t)NROWS*EMB)
#define NSS   ((size_t)BATCH*SEQ*SEQ)
#define WSZ   ((size_t)1024*1024)

// GEMM tiling
#define BM 128
#define BN 128
#define BK 32
#define NQ  (KDIM/BK)   // 32 K-chunks
#define LDS 40          // padded smem row stride (elements)

#define TILE_B      (BM*LDS*2)              // 10240 bytes per 128x32 fp16 tile
#define NST1 4                              // pipeline depth
#define SMEM_NP1    (NST1*2*TILE_B)         // 81920 -> 2 CTAs/SM
// trans-epilogue transpose buffer: 128 x (128+8) halves = 34816 B (< SMEM_NP1)
#define TLDS 136

// ---------------- PTX helpers (portable sm_80+ only) ----------------
__device__ __forceinline__ unsigned smem_u32(const void* p) {
    unsigned a;
    asm("{ .reg .u64 t; cvta.to.shared.u64 t, %1; cvt.u32.u64 %0, t; }" : "=r"(a) : "l"(p));
    return a;
}
#define CPASYNC16(dst, src) \
    asm volatile("cp.async.cg.shared.global [%0], [%1], 16;" :: "r"(dst), "l"(src))
#define CPCOMMIT() asm volatile("cp.async.commit_group;" ::: "memory")
#define CPWAIT(n)  asm volatile("cp.async.wait_group %0;" :: "n"(n) : "memory")
#define LDSM4(r0, r1, r2, r3, a) \
    asm volatile("ldmatrix.sync.aligned.m8n8.x4.shared.b16 {%0,%1,%2,%3}, [%4];" \
        : "=r"(r0), "=r"(r1), "=r"(r2), "=r"(r3) : "r"(a))
#define MMA(c, a, b) \
    asm volatile("mma.sync.aligned.m16n8k16.row.col.f32.f16.f16.f32 " \
        "{%0,%1,%2,%3}, {%4,%5,%6,%7}, {%8,%9}, {%0,%1,%2,%3};" \
        : "+f"((c)[0]), "+f"((c)[1]), "+f"((c)[2]), "+f"((c)[3]) \
        : "r"((a)[0]), "r"((a)[1]), "r"((a)[2]), "r"((a)[3]), "r"((b)[0]), "r"((b)[1]))

// ---------------- scratch ----------------
__device__ float g_x[NELEM];                       // residual stream (fp32)
__device__ float g_y[NELEM];                       // x2 (fp32)
__device__ __half g_h_hi[NELEM];                   // LN out / attn out (fp16)
__device__ __half g_q_hi[NELEM];                   // q; later f1 (fp16)
__device__ __half g_k_hi[NELEM];                   // k
__device__ __half g_vT_hi[NELEM];                  // v transposed
__device__ __half g_w_hi[NSS];                     // softmax weights (fp16)
__device__ __half g_W_hi[6*WSZ];                   // weights (fp16)

// ---------------------------------------------------------------------------
// Tensor-core GEMM: C = alpha*(A @ B^T) [+bias] [+Rsd] [relu], plain fp16.
// NQ K-chunks, NST-deep cp.async pipeline, 1 barrier/chunk, 2 CTAs/SM.
// grid = (N/128, M/128, Z). Outputs: fp32 Cf and/or fp16 Ch;
// trans=1 stores C[r,e] at [(b*1024+e)*1024 + s] via smem transpose.
// ---------------------------------------------------------------------------
template<int NST>
__global__ void __launch_bounds__(256, 2) gemm_mma(
    const __half* __restrict__ Ah, size_t sA,
    const __half* __restrict__ Bh, size_t sB,
    const float* __restrict__ bias,
    const float* __restrict__ Rsd, size_t sR,
    float alpha, int relu,
    float* __restrict__ Cf,
    __half* __restrict__ Ch,
    int trans, size_t sC)
{
    extern __shared__ __align__(16) char dynsm[];
    const unsigned dynB = smem_u32(dynsm);
    constexpr unsigned STG = 2 * TILE_B;              // per-stage bytes (A,B)
    constexpr unsigned OFFB = TILE_B;                 // B-tile offset in stage

    const int tid = threadIdx.x, wid = tid >> 5, lane = tid & 31;
    const int wm = wid & 3, wn = wid >> 2;            // warp grid 4(m) x 2(n)
    const int g = lane >> 2, tig = lane & 3;
    const int bm = blockIdx.y * BM, bn = blockIdx.x * BN;
    const int z = blockIdx.z;
    Ah += (size_t)z * sA;
    Bh += (size_t)z * sB;

    // staging: thread -> (row, 8-elem col group); 2 iters cover 128 rows
    const int srow = tid >> 2, sc = (tid & 3) * 8;
    // ldmatrix per-thread base offsets (bytes) — validated mapping
    const unsigned aoff0 = (unsigned)((wm * 32 + (lane & 15)) * LDS + (lane >> 4) * 8) * 2;
    const unsigned boff0 = (unsigned)((wn * 64 + (lane >> 4) * 8 + (lane & 7)) * LDS
                                      + ((lane >> 3) & 1) * 8) * 2;

    float acc[2][8][4];
#pragma unroll
    for (int a = 0; a < 2; a++)
#pragma unroll
        for (int b = 0; b < 8; b++)
#pragma unroll
            for (int c = 0; c < 4; c++) acc[a][b][c] = 0.f;

    auto stage = [&](int q, int buf) {
        const int ko = q * BK;
        const unsigned d = dynB + (unsigned)buf * STG;
#pragma unroll
        for (int i = 0; i < 2; i++) {
            const int row = srow + i * 64;
            const unsigned so = (unsigned)(row * LDS + sc) * 2;
            const size_t ga = (size_t)(bm + row) * KDIM + ko + sc;
            const size_t gb = (size_t)(bn + row) * KDIM + ko + sc;
            CPASYNC16(d + so, (const void*)(Ah + ga));
            CPASYNC16(d + OFFB + so, (const void*)(Bh + gb));
        }
    };

    auto compute = [&](int buf) {
        const unsigned sb = dynB + (unsigned)buf * STG;
#pragma unroll
        for (int ks = 0; ks < 2; ks++) {
            const unsigned kof = (unsigned)(ks * 16) * 2;
            unsigned afh[2][4];
#pragma unroll
            for (int mi = 0; mi < 2; mi++) {
                const unsigned mof = aoff0 + (unsigned)(mi * 16 * LDS) * 2 + kof;
                LDSM4(afh[mi][0], afh[mi][1], afh[mi][2], afh[mi][3], sb + mof);
            }
            unsigned bfh[8][2];
#pragma unroll
            for (int jp = 0; jp < 4; jp++) {
                const unsigned nof = boff0 + (unsigned)(jp * 16 * LDS) * 2 + kof;
                unsigned r0, r1, r2, r3;
                LDSM4(r0, r1, r2, r3, sb + OFFB + nof);
                bfh[jp*2][0] = r0; bfh[jp*2][1] = r1;
                bfh[jp*2+1][0] = r2; bfh[jp*2+1][1] = r3;
            }
#pragma unroll
            for (int mi = 0; mi < 2; mi++)
#pragma unroll
                for (int ni = 0; ni < 8; ni++)
                    MMA(acc[mi][ni], afh[mi], bfh[ni]);
        }
    };

    // prologue: prefetch stages 0..NST-2
#pragma unroll
    for (int s = 0; s < NST - 1; s++) { stage(s, s); CPCOMMIT(); }

    for (int q = 0; q < NQ; q++) {
        CPWAIT(NST - 2);
        __syncthreads();
        if (q + NST - 1 < NQ) stage(q + NST - 1, (q + NST - 1) & (NST - 1));
        CPCOMMIT();
        compute(q & (NST - 1));
    }

    // ---- epilogue ----
    if (Ch && trans) {
        // smem transpose -> coalesced stores along s
        __syncthreads();
        __half* ts = (__half*)dynsm;    // [128 cols e][TLDS] layout
#pragma unroll
        for (int mi = 0; mi < 2; mi++)
#pragma unroll
            for (int half = 0; half < 2; half++) {
                const int rl = wm * 32 + mi * 16 + g + half * 8;   // tile-local row (s)
#pragma unroll
                for (int ni = 0; ni < 8; ni++) {
                    const int cl = wn * 64 + ni * 8 + tig * 2;     // tile-local col (e)
                    ts[(cl)     * TLDS + rl] = __float2half_rn(acc[mi][ni][half*2+0] * alpha
                                               + (bias ? __ldg(bias + bn + cl)     : 0.f));
                    ts[(cl + 1) * TLDS + rl] = __float2half_rn(acc[mi][ni][half*2+1] * alpha
                                               + (bias ? __ldg(bias + bn + cl + 1) : 0.f));
                }
            }
        __syncthreads();
        // r = bm + s_local; whole tile lies in one batch b
        const size_t b = (size_t)bm >> 10, s0 = (size_t)bm & 1023;
        const int col = tid >> 1, hhalf = (tid & 1) * 64;          // 128 cols x 2 halves
        __half* dst = Ch + ((b << 10) + (size_t)(bn + col)) * 1024 + s0 + hhalf;
        const __half* src = ts + col * TLDS + hhalf;
#pragma unroll
        for (int j = 0; j < 8; j++)
            *(uint4*)(dst + j * 8) = *(const uint4*)(src + j * 8);
        return;
    }

#pragma unroll
    for (int mi = 0; mi < 2; mi++) {
#pragma unroll
        for (int half = 0; half < 2; half++) {
            const int r = bm + wm * 32 + mi * 16 + g + half * 8;
#pragma unroll
            for (int ni = 0; ni < 8; ni++) {
                const int cc = bn + wn * 64 + ni * 8 + tig * 2;
                float v0 = acc[mi][ni][half * 2 + 0] * alpha;
                float v1 = acc[mi][ni][half * 2 + 1] * alpha;
                if (bias) { v0 += __ldg(bias + cc); v1 += __ldg(bias + cc + 1); }
                if (Rsd) {
                    const float2 rv = *(const float2*)(Rsd + (size_t)z * sR
                                                       + (size_t)r * 1024 + cc);
                    v0 += rv.x; v1 += rv.y;
                }
                if (relu) { v0 = fmaxf(v0, 0.f); v1 = fmaxf(v1, 0.f); }
                if (Cf)
                    *(float2*)(Cf + (size_t)z * sC + (size_t)r * 1024 + cc)
                        = make_float2(v0, v1);
                if (Ch)
                    *(__half2*)(Ch + (size_t)z * sC + (size_t)r * 1024 + cc)
                        = __halves2half2(__float2half_rn(v0), __float2half_rn(v1));
            }
        }
    }
}

// ---------------------------------------------------------------------------
__global__ __launch_bounds__(256) void embed_k(const float* __restrict__ x,
                                               const float* __restrict__ pe,
                                               float* __restrict__ o) {
    size_t i = (size_t)blockIdx.x * 256 + threadIdx.x;
    const float4 a = ((const float4*)x)[i];
    const float4 p = ((const float4*)pe)[i & ((size_t)SEQ * EMB / 4 - 1)];
    ((float4*)o)[i] = make_float4(32.f*a.x+p.x, 32.f*a.y+p.y, 32.f*a.z+p.z, 32.f*a.w+p.w);
}

// fp16 truncation (weights)
__global__ __launch_bounds__(256) void splithi_k(const float* __restrict__ in,
                                                 __half* __restrict__ oh) {
    size_t i = ((size_t)blockIdx.x * 256 + threadIdx.x) * 4;
    float4 v = *(const float4*)(in + i);
    *(__half2*)(oh + i)     = __halves2half2(__float2half_rn(v.x), __float2half_rn(v.y));
    *(__half2*)(oh + i + 2) = __halves2half2(__float2half_rn(v.z), __float2half_rn(v.w));
}

// LayerNorm -> fp16
__global__ __launch_bounds__(256) void ln_hi_k(const float* __restrict__ in,
                                               const float* __restrict__ g,
                                               const float* __restrict__ b,
                                               __half* __restrict__ oh) {
    const size_t row = blockIdx.x;
    const int t = threadIdx.x;
    const float4 v = ((const float4*)(in + row * EMB))[t];
    float s  = v.x + v.y + v.z + v.w;
    float ss = v.x*v.x + v.y*v.y + v.z*v.z + v.w*v.w;
#pragma unroll
    for (int o = 16; o > 0; o >>= 1) {
        s  += __shfl_xor_sync(0xFFFFFFFFu, s, o);
        ss += __shfl_xor_sync(0xFFFFFFFFu, ss, o);
    }
    __shared__ float sh_s[8], sh_ss[8];
    if ((t & 31) == 0) { sh_s[t >> 5] = s; sh_ss[t >> 5] = ss; }
    __syncthreads();
    float ts = 0.f, tss = 0.f;
#pragma unroll
    for (int i = 0; i < 8; i++) { ts += sh_s[i]; tss += sh_ss[i]; }
    const float mu  = ts * (1.f / EMB);
    const float inv = rsqrtf(tss * (1.f / EMB) - mu * mu + 1e-5f);
    const float4 gg = ((const float4*)g)[t];
    const float4 bb = ((const float4*)b)[t];
    float r0 = (v.x - mu) * inv * gg.x + bb.x;
    float r1 = (v.y - mu) * inv * gg.y + bb.y;
    float r2 = (v.z - mu) * inv * gg.z + bb.z;
    float r3 = (v.w - mu) * inv * gg.w + bb.w;
    size_t o4 = row * EMB + (size_t)t * 4;
    *(__half2*)(oh + o4)     = __halves2half2(__float2half_rn(r0), __float2half_rn(r1));
    *(__half2*)(oh + o4 + 2) = __halves2half2(__float2half_rn(r2), __float2half_rn(r3));
}

// softmax in place (fp32) + fp16 output
__global__ __launch_bounds__(256) void softmax_k(float* __restrict__ w,
                                                 __half* __restrict__ oh) {
    const size_t row = blockIdx.x;
    float4* p = (float4*)(w + row * SEQ);
    const int t = threadIdx.x;
    float4 v = p[t];
    float m = fmaxf(fmaxf(v.x, v.y), fmaxf(v.z, v.w));
#pragma unroll
    for (int o = 16; o > 0; o >>= 1) m = fmaxf(m, __shfl_xor_sync(0xFFFFFFFFu, m, o));
    __shared__ float shm[8], shs[8];
    if ((t & 31) == 0) shm[t >> 5] = m;
    __syncthreads();
    float M = shm[0];
#pragma unroll
    for (int i = 1; i < 8; i++) M = fmaxf(M, shm[i]);
    float4 e;
    e.x = __expf(v.x - M); e.y = __expf(v.y - M);
    e.z = __expf(v.z - M); e.w = __expf(v.w - M);
    float s = e.x + e.y + e.z + e.w;
#pragma unroll
    for (int o = 16; o > 0; o >>= 1) s += __shfl_xor_sync(0xFFFFFFFFu, s, o);
    if ((t & 31) == 0) shs[t >> 5] = s;
    __syncthreads();
    float S = 0.f;
#pragma unroll
    for (int i = 0; i < 8; i++) S += shs[i];
    const float inv = 1.f / S;
    e.x *= inv; e.y *= inv; e.z *= inv; e.w *= inv;
    p[t] = e;
    size_t o4 = row * SEQ + (size_t)t * 4;
    *(__half2*)(oh + o4)     = __halves2half2(__float2half_rn(e.x), __float2half_rn(e.y));
    *(__half2*)(oh + o4 + 2) = __halves2half2(__float2half_rn(e.z), __float2half_rn(e.w));
}

__global__ __launch_bounds__(256) void cls_k(const float* __restrict__ X,
                                             const float* __restrict__ Wc,
                                             const float* __restrict__ bc,
                                             float* __restrict__ out) {
    const int b = blockIdx.x >> 1, o = blockIdx.x & 1;
    const int t = threadIdx.x;
    const float4 a = ((const float4*)(X + (size_t)b * SEQ * EMB))[t];
    const float4 w = ((const float4*)(Wc + (size_t)o * EMB))[t];
    float s = a.x*w.x + a.y*w.y + a.z*w.z + a.w*w.w;
#pragma unroll
    for (int off = 16; off > 0; off >>= 1) s += __shfl_xor_sync(0xFFFFFFFFu, s, off);
    __shared__ float sh[8];
    if ((t & 31) == 0) sh[t >> 5] = s;
    __syncthreads();
    if (t == 0) {
        float S = 0.f;
#pragma unroll
        for (int i = 0; i < 8; i++) S += sh[i];
        out[b * 2 + o] = S + bc[o];
    }
}

// ---------------------------------------------------------------------------
extern "C" void kernel_launch(void* const* d_in, const int* in_sizes, int n_in,
                              void* d_out, int out_size) {
    (void)in_sizes; (void)n_in; (void)out_size;
    const float* x     = (const float*)d_in[0];
    const float* pe    = (const float*)d_in[1];
    const float* ln1_g = (const float*)d_in[2];
    const float* ln1_b = (const float*)d_in[3];
    const float* Wq = (const float*)d_in[4];  const float* bq = (const float*)d_in[5];
    const float* Wk = (const float*)d_in[6];  const float* bk = (const float*)d_in[7];
    const float* Wv = (const float*)d_in[8];  const float* bv = (const float*)d_in[9];
    const float* Wo = (const float*)d_in[10]; const float* bo = (const float*)d_in[11];
    const float* ln2_g = (const float*)d_in[12];
    const float* ln2_b = (const float*)d_in[13];
    const float* W1 = (const float*)d_in[14]; const float* b1 = (const float*)d_in[15];
    const float* W2 = (const float*)d_in[16]; const float* b2 = (const float*)d_in[17];
    const float* Wc = (const float*)d_in[18]; const float* bc = (const float*)d_in[19];

    float* out = (float*)d_out;
    float* w1 = out + 64;
    float* w2 = w1 + NSS;

    float *px, *py;
    __half *hh, *qh, *kh, *vh, *wh, *Wh;
    cudaGetSymbolAddress((void**)&px, g_x);
    cudaGetSymbolAddress((void**)&py, g_y);
    cudaGetSymbolAddress((void**)&hh, g_h_hi);
    cudaGetSymbolAddress((void**)&qh, g_q_hi);
    cudaGetSymbolAddress((void**)&kh, g_k_hi);
    cudaGetSymbolAddress((void**)&vh, g_vT_hi);
    cudaGetSymbolAddress((void**)&wh, g_w_hi);
    cudaGetSymbolAddress((void**)&Wh, g_W_hi);

    cudaFuncSetAttribute(gemm_mma<NST1>, cudaFuncAttributeMaxDynamicSharedMemorySize, SMEM_NP1);
    cudaFuncSetAttribute(gemm_mma<NST1>, cudaFuncAttributePreferredSharedMemoryCarveout, 100);

    const size_t sSE = (size_t)SEQ * EMB;
    const size_t sSS = (size_t)SEQ * SEQ;

    // weight truncation
    const float* Ws[6] = {Wq, Wk, Wv, Wo, W1, W2};
    for (int i = 0; i < 6; i++)
        splithi_k<<<1024, 256>>>(Ws[i], Wh + (size_t)i * WSZ);
    __half *Wqh = Wh,         *Wkh = Wh + WSZ,   *Wvh = Wh + 2*WSZ;
    __half *Woh = Wh + 3*WSZ, *W1h = Wh + 4*WSZ, *W2h = Wh + 5*WSZ;

    // x1 = 32*x + pe
    embed_k<<<(unsigned)(NELEM / 4 / 256), 256>>>(x, pe, px);

    const dim3 gP(EMB / BN, NROWS / BM, 1);     // (8, 256, 1)
    const dim3 gB(SEQ / BN, SEQ / BM, BATCH);   // (8, 8, 32)

    for (int blk = 0; blk < 2; blk++) {
        float* wout = blk ? w2 : w1;
        // h = LN1(x) -> fp16
        ln_hi_k<<<NROWS, 256>>>(px, ln1_g, ln1_b, hh);
        // q = h@Wq^T + bq -> fp16
        gemm_mma<NST1><<<gP, 256, SMEM_NP1>>>(hh, 0, Wqh, 0, bq, nullptr, 0,
                                              1.f, 0, nullptr, qh, 0, 0);
        // k -> fp16
        gemm_mma<NST1><<<gP, 256, SMEM_NP1>>>(hh, 0, Wkh, 0, bk, nullptr, 0,
                                              1.f, 0, nullptr, kh, 0, 0);
        // v -> fp16 transposed (attn B operand)
        gemm_mma<NST1><<<gP, 256, SMEM_NP1>>>(hh, 0, Wvh, 0, bv, nullptr, 0,
                                              1.f, 0, nullptr, vh, 1, 0);
        // scores = q k^T / 32 -> fp32 wout (straight into d_out region)
        gemm_mma<NST1><<<gB, 256, SMEM_NP1>>>(qh, sSE, kh, sSE, nullptr, nullptr, 0,
                                              0.03125f, 0, wout, nullptr, 0, sSS);
        // softmax in place + fp16
        softmax_k<<<NROWS, 256>>>(wout, wh);
        // attn = w @ vT^T -> fp16 into h (reuse)
        gemm_mma<NST1><<<gB, 256, SMEM_NP1>>>(wh, sSS, vh, sSE, nullptr, nullptr, 0,
                                              1.f, 0, nullptr, hh, 0, sSE);
        // x2 = x1 + attn@Wo^T + bo -> fp32 py
        gemm_mma<NST1><<<gP, 256, SMEM_NP1>>>(hh, 0, Woh, 0, bo, px, 0,
                                              1.f, 0, py, nullptr, 0, 0);
        // h = LN2(x2) -> fp16
        ln_hi_k<<<NROWS, 256>>>(py, ln2_g, ln2_b, hh);
        // f1 = relu(h@W1^T + b1) -> fp16 into q (reuse)
        gemm_mma<NST1><<<gP, 256, SMEM_NP1>>>(hh, 0, W1h, 0, b1, nullptr, 0,
                                              1.f, 1, nullptr, qh, 0, 0);
        // x3 = x2 + f1@W2^T + b2 -> fp32 px
        gemm_mma<NST1><<<gP, 256, SMEM_NP1>>>(qh, 0, W2h, 0, b2, py, 0,
                                              1.f, 0, px, nullptr, 0, 0);
    }

    cls_k<<<64, 256>>>(px, Wc, bc, out);
}